// round 11
// baseline (speedup 1.0000x reference)
#include <cuda_runtime.h>
#include <cuda_bf16.h>
#include <math.h>
#include <stdint.h>

// ---------------- problem constants ----------------
#define BB        64
#define NN        128
#define FLAT      8192          // B*N
#define H_DIM     128
#define NODE_S    64
#define NODE_V    32
#define OUT_S     32
#define OUT_V     16
#define OUT_DIM   80
#define HIDN      128
#define NEE       512
#define EATT_N    4096
#define WN        4608
#define CUTOFF_F  5.0f
#define NORM_F    0.10206207261596575f   // 1/sqrt(96)
#define SQRT3_F   1.7320508075688772f
#define NACT_MAX  4096
#define ROWS3     32768         // B * NE
#define KWIN      64            // padded 49
#define KGIN      288           // padded 273

// ---------------- scratch (static device memory) ----------------
__device__ int   g_winner[FLAT];
__device__ int   g_active[FLAT];
__device__ int   g_posmap[FLAT];
__device__ int   g_count;
__device__ float g_ghid  [NACT_MAX * HIDN];
__device__ float g_env   [NACT_MAX];
__device__ float g_mul   [NACT_MAX];
__device__ float g_u     [NACT_MAX * 3];
__device__ float g_tpw   [NACT_MAX * WN];     // 75.5 MB
__device__ float g_vec   [NACT_MAX * OUT_DIM];
__device__ float g_vpart [BB * 4 * OUT_DIM];
__device__ float g_vabs  [BB * OUT_DIM];
__device__ float g_scales[NEE * 48];

// pre-split bf16 hi/lo packed operands (u32 = bf16x2 over consecutive k)
// activations: [row][K/2];  weights: [n][K/2] (transposed at split time)
__device__ __align__(16) unsigned g_winH[NACT_MAX * (KWIN/2)];
__device__ __align__(16) unsigned g_winL[NACT_MAX * (KWIN/2)];
__device__ __align__(16) unsigned g_ginH[NACT_MAX * (KGIN/2)];
__device__ __align__(16) unsigned g_ginL[NACT_MAX * (KGIN/2)];
__device__ __align__(16) unsigned g_hidH[NACT_MAX * (HIDN/2)];
__device__ __align__(16) unsigned g_hidL[NACT_MAX * (HIDN/2)];
__device__ __align__(16) unsigned g_invH[ROWS3 * 24];
__device__ __align__(16) unsigned g_invL[ROWS3 * 24];
__device__ __align__(16) unsigned g_x1H[ROWS3 * 64];
__device__ __align__(16) unsigned g_x1L[ROWS3 * 64];
__device__ __align__(16) unsigned g_x2H[ROWS3 * 64];
__device__ __align__(16) unsigned g_x2L[ROWS3 * 64];
__device__ __align__(16) unsigned g_wg1H[128 * 144];
__device__ __align__(16) unsigned g_wg1L[128 * 144];
__device__ __align__(16) unsigned g_w1H[128 * 32];
__device__ __align__(16) unsigned g_w1L[128 * 32];
__device__ __align__(16) unsigned g_w2H[4608 * 64];
__device__ __align__(16) unsigned g_w2L[4608 * 64];
__device__ __align__(16) unsigned g_wo1H[128 * 24];
__device__ __align__(16) unsigned g_wo1L[128 * 24];
__device__ __align__(16) unsigned g_wo2H[128 * 64];
__device__ __align__(16) unsigned g_wo2L[128 * 64];
__device__ __align__(16) unsigned g_wo3H[256 * 64];
__device__ __align__(16) unsigned g_wo3L[256 * 64];

__device__ __forceinline__ float siluf(float x) { return x / (1.0f + expf(-x)); }
__device__ __forceinline__ float sigmoidf_(float x) { return 1.0f / (1.0f + expf(-x)); }

__device__ __forceinline__ unsigned smem_u32(const void* p) {
    return (unsigned)__cvta_generic_to_shared(p);
}

// split a pair of fp32 into hi/lo bf16x2 packed words (low half = first elem)
__device__ __forceinline__ void split2(float x, float y, unsigned& hi, unsigned& lo) {
    __nv_bfloat162 hh = __floats2bfloat162_rn(x, y);
    float hx = __bfloat162float(__low2bfloat16(hh));
    float hy = __bfloat162float(__high2bfloat16(hh));
    __nv_bfloat162 ll = __floats2bfloat162_rn(x - hx, y - hy);
    hi = *reinterpret_cast<unsigned*>(&hh);
    lo = *reinterpret_cast<unsigned*>(&ll);
}

#define MMA_BF16(c, a, b)                                                        \
    asm volatile(                                                                \
        "mma.sync.aligned.m16n8k16.row.col.f32.bf16.bf16.f32 "                   \
        "{%0,%1,%2,%3},{%4,%5,%6,%7},{%8,%9},{%0,%1,%2,%3};"                     \
        : "+f"((c)[0]), "+f"((c)[1]), "+f"((c)[2]), "+f"((c)[3])                 \
        : "r"((a)[0]), "r"((a)[1]), "r"((a)[2]), "r"((a)[3]),                    \
          "r"((b)[0]), "r"((b)[1]))

#define LDSM4(R0, R1, R2, R3, ADDR)                                              \
    asm volatile(                                                                \
        "ldmatrix.sync.aligned.m8n8.x4.shared.b16 {%0,%1,%2,%3}, [%4];"          \
        : "=r"(R0), "=r"(R1), "=r"(R2), "=r"(R3) : "r"(ADDR))

// ---------------- k_initw: winner init + weight pre-split (merged) -------------
// weight split output layout: [n][K/2] u32 (pair over k). segments:
// wg1(128n x 144) w1(128 x 32) w2(4608 x 64) wo1(128 x 24) wo2(128 x 64) wo3(256 x 64)
#define SEG0 18432
#define SEG1 22528
#define SEG2 317440
#define SEG3 320512
#define SEG4 328704
#define SEG5 345088
__global__ void k_initw(const float* __restrict__ wg1, const float* __restrict__ w1,
                        const float* __restrict__ w2,  const float* __restrict__ wo1,
                        const float* __restrict__ wo2, const float* __restrict__ wo3)
{
    int i = blockIdx.x * blockDim.x + threadIdx.x;
    if (i < FLAT) g_winner[i] = -1;
    if (i == 0)   g_count = 0;
    if (i >= SEG5) return;
    const float* src; unsigned *H, *L; int Nn, K2, Kreal, li;
    if (i < SEG0)      { src = wg1; H = g_wg1H; L = g_wg1L; Nn = 128;  K2 = 144; Kreal = 273; li = i; }
    else if (i < SEG1) { src = w1;  H = g_w1H;  L = g_w1L;  Nn = 128;  K2 = 32;  Kreal = 49;  li = i - SEG0; }
    else if (i < SEG2) { src = w2;  H = g_w2H;  L = g_w2L;  Nn = 4608; K2 = 64;  Kreal = 128; li = i - SEG1; }
    else if (i < SEG3) { src = wo1; H = g_wo1H; L = g_wo1L; Nn = 128;  K2 = 24;  Kreal = 48;  li = i - SEG2; }
    else if (i < SEG4) { src = wo2; H = g_wo2H; L = g_wo2L; Nn = 128;  K2 = 64;  Kreal = 128; li = i - SEG3; }
    else               { src = wo3; H = g_wo3H; L = g_wo3L; Nn = 256;  K2 = 64;  Kreal = 128; li = i - SEG4; }
    int n = li / K2, kp = li - n * K2;
    int k0 = 2 * kp;
    float x = (k0 < Kreal)     ? src[(size_t)k0 * Nn + n]       : 0.0f;
    float y = (k0 + 1 < Kreal) ? src[(size_t)(k0 + 1) * Nn + n] : 0.0f;
    unsigned hi, lo;
    split2(x, y, hi, lo);
    H[li] = hi; L[li] = lo;
}

// ---------------- scatter: last-write-wins == max edge index ----------------
__global__ void k_scatter(const int* __restrict__ att_dst) {
    int e = blockIdx.x * blockDim.x + threadIdx.x;
    if (e < EATT_N) atomicMax(&g_winner[att_dst[e]], e);
}

__global__ void k_compact() {
    int i = blockIdx.x * blockDim.x + threadIdx.x;
    if (i < FLAT && g_winner[i] >= 0) {
        int p = atomicAdd(&g_count, 1);
        g_active[p] = i;
        g_posmap[i] = p;
    }
}

// ---------------- k_prep: split input rows per active node (+scales merged) ----
__global__ void __launch_bounds__(128)
k_prep(const float* __restrict__ h,
       const int*   __restrict__ z,
       const int*   __restrict__ absorber_index,
       const float* __restrict__ att_dist,
       const float* __restrict__ att_vec,
       const float* __restrict__ w_zemb,
       const float* __restrict__ e_feat,
       const float* __restrict__ we1, const float* __restrict__ be1,
       const float* __restrict__ we2, const float* __restrict__ be2)
{
    const int tid = threadIdx.x;
    if (blockIdx.x >= NACT_MAX) {
        // ---- scales MLP for edge type e ----
        __shared__ float hidd[HIDN];
        int e = blockIdx.x - NACT_MAX;
        float acc = be1[tid];
        for (int k = 0; k < 16; k++) acc += e_feat[e * 16 + k] * we1[k * HIDN + tid];
        hidd[tid] = siluf(acc);
        __syncthreads();
        if (tid < 48) {
            float s = be2[tid];
            for (int k = 0; k < HIDN; k++) s += hidd[k] * we2[k * 48 + tid];
            g_scales[e * 48 + tid] = s;
        }
        return;
    }
    const int pos = blockIdx.x;
    if (pos >= g_count) return;
    const int node = g_active[pos];
    const int b = node >> 7, n = node & 127;
    const int e = g_winner[node];
    const float d = att_dist[e];
    const int absb = absorber_index[b];
    const float isabs = (n == absb) ? 1.0f : 0.0f;
    const float width = CUTOFF_F / 15.0f;
    const float invwidth = 15.0f / CUTOFF_F;
    unsigned hi, lo;

    // ---- win row (64 padded, 49 used): [zemb 32 | isabs | rbf 16 | pad] ----
    if (tid < KWIN) {
        float v = 0.0f;
        if (tid < 32)       v = w_zemb[z[node] * 32 + tid];
        else if (tid == 32) v = isabs;
        else if (tid < 49) {
            float t = (d - (float)(tid - 33) * width) * invwidth;
            v = expf(-0.5f * t * t);
        }
        float vp = __shfl_xor_sync(0xffffffffu, v, 1);
        if (!(tid & 1)) {
            split2(v, vp, hi, lo);
            g_winH[pos * 32 + (tid >> 1)] = hi;
            g_winL[pos * 32 + (tid >> 1)] = lo;
        }
    }
    // ---- gin row (288 padded, 273 used) ----
    {
        float v = h[(b * NN + absb) * H_DIM + tid];
        float vp = __shfl_xor_sync(0xffffffffu, v, 1);
        if (!(tid & 1)) {
            split2(v, vp, hi, lo);
            g_ginH[pos * 144 + (tid >> 1)] = hi;
            g_ginL[pos * 144 + (tid >> 1)] = lo;
        }
    }
    {
        float v = h[node * H_DIM + tid];
        float vp = __shfl_xor_sync(0xffffffffu, v, 1);
        if (!(tid & 1)) {
            split2(v, vp, hi, lo);
            g_ginH[pos * 144 + 64 + (tid >> 1)] = hi;
            g_ginL[pos * 144 + 64 + (tid >> 1)] = lo;
        }
    }
    if (tid < 32) {
        float v = 0.0f;
        if (tid < 16) {
            float t = (d - (float)tid * width) * invwidth;
            v = expf(-0.5f * t * t);
        } else if (tid == 16) v = isabs;
        float vp = __shfl_xor_sync(0xffffffffu, v, 1);
        if (!(tid & 1)) {
            split2(v, vp, hi, lo);
            g_ginH[pos * 144 + 128 + (tid >> 1)] = hi;
            g_ginL[pos * 144 + 128 + (tid >> 1)] = lo;
        }
    }
    if (tid == 0)
        g_env[pos] = (d < CUTOFF_F) ? 0.5f * (cospif(d / CUTOFF_F) + 1.0f) : 0.0f;
    if (tid < 3)
        g_u[pos * 3 + tid] = att_vec[e * 3 + tid] / fmaxf(d, 1e-8f);
}

// ---------------- k_gate2 ----------------
__global__ void __launch_bounds__(256)
k_gate2(const float* __restrict__ wg2, const float* __restrict__ bg2)
{
    int wid = threadIdx.x >> 5, lane = threadIdx.x & 31;
    int pos = blockIdx.x * 8 + wid;
    if (pos >= g_count) return;
    float s = 0.0f;
#pragma unroll
    for (int j = 0; j < 4; j++) {
        int k = lane + 32 * j;
        s += g_ghid[pos * HIDN + k] * wg2[k];
    }
#pragma unroll
    for (int off = 16; off > 0; off >>= 1) s += __shfl_xor_sync(0xffffffffu, s, off);
    if (lane == 0)
        g_mul[pos] = sigmoidf_(s + bg2[0]) * g_env[pos] * NORM_F;
}

// ================= split-bf16 tensor-core GEMM (ldmatrix fragments) ============
// C = act(A @ W + bias). Block tile 128x64, BK=16, 256 threads, 8 warps 4x2,
// warp tile 32x32 via m16n8k16. D = AhBh + AhBl + AlBh.
// A: [M][K/2] u32;  W: [n][K/2] u32 (weight pre-transposed at split).
// smem: both tiles row-major [row][kpair] with stride 12 u32 (48B) --
// rows hit distinct 16B banks (48r mod 128 -> 0,3,6,1,4,7,2,5), so ldmatrix and
// uint4 staging are conflict-free. Double-buffered, 1 sync/k16.
// mode: 0 = f32 out, 1 = f32 + silu, 2 = split(hi/lo) + silu.
__global__ void __launch_bounds__(256, 2)
k_bmma(const unsigned* __restrict__ Ah_g, const unsigned* __restrict__ Al_g,
       const unsigned* __restrict__ Wh_g, const unsigned* __restrict__ Wl_g,
       const float* __restrict__ bias,
       float* __restrict__ Cf, unsigned* __restrict__ CH, unsigned* __restrict__ CL,
       int M, int N, int K, int mode)
{
    __shared__ __align__(16) unsigned sAh[2][128 * 12];
    __shared__ __align__(16) unsigned sAl[2][128 * 12];
    __shared__ __align__(16) unsigned sWh[2][64 * 12];
    __shared__ __align__(16) unsigned sWl[2][64 * 12];

    const int tid = threadIdx.x;
    const int wid = tid >> 5, lane = tid & 31;
    const int wm = wid & 3, wn = wid >> 2;
    const int g = lane >> 2, tig = lane & 3;
    const int m0 = blockIdx.y * 128, n0 = blockIdx.x * 64;
    const int K2 = K >> 1;
    const int nk = K >> 4;

    // staging indices
    const int ar = tid >> 1, akp = (tid & 1) * 4;      // A: 128 rows x 2 halves
    const int br = tid & 63, bkp = ((tid >> 6) & 1) * 4;  // B: 64 rows x 2 halves (tid<128)

    // ldmatrix per-lane offsets (bytes within a buffer)
    const int sel = lane >> 3;
    const int lrow = (lane & 7) + (sel & 1) * 8;
    const int lcol = (sel >> 1) * 4;
    const unsigned offA0 = ((wm * 32 + lrow) * 12 + lcol) * 4;
    const unsigned offA1 = ((wm * 32 + 16 + lrow) * 12 + lcol) * 4;
    const unsigned offB0 = ((wn * 32 + lrow) * 12 + lcol) * 4;
    const unsigned offB1 = ((wn * 32 + 16 + lrow) * 12 + lcol) * 4;

    float cacc[2][4][4];
#pragma unroll
    for (int mt = 0; mt < 2; mt++)
#pragma unroll
        for (int nt = 0; nt < 4; nt++)
#pragma unroll
            for (int i = 0; i < 4; i++) cacc[mt][nt][i] = 0.0f;

    // prefetch tile 0
    uint4 pah = *reinterpret_cast<const uint4*>(Ah_g + (size_t)(m0 + ar) * K2 + akp);
    uint4 pal = *reinterpret_cast<const uint4*>(Al_g + (size_t)(m0 + ar) * K2 + akp);
    uint4 pwh = make_uint4(0, 0, 0, 0), pwl = make_uint4(0, 0, 0, 0);
    if (tid < 128) {
        pwh = *reinterpret_cast<const uint4*>(Wh_g + (size_t)(n0 + br) * K2 + bkp);
        pwl = *reinterpret_cast<const uint4*>(Wl_g + (size_t)(n0 + br) * K2 + bkp);
    }

    for (int it = 0; it < nk; it++) {
        const int buf = it & 1;
        *reinterpret_cast<uint4*>(&sAh[buf][ar * 12 + akp]) = pah;
        *reinterpret_cast<uint4*>(&sAl[buf][ar * 12 + akp]) = pal;
        if (tid < 128) {
            *reinterpret_cast<uint4*>(&sWh[buf][br * 12 + bkp]) = pwh;
            *reinterpret_cast<uint4*>(&sWl[buf][br * 12 + bkp]) = pwl;
        }
        if (it + 1 < nk) {
            int kp0 = (it + 1) * 8;
            pah = *reinterpret_cast<const uint4*>(Ah_g + (size_t)(m0 + ar) * K2 + kp0 + akp);
            pal = *reinterpret_cast<const uint4*>(Al_g + (size_t)(m0 + ar) * K2 + kp0 + akp);
            if (tid < 128) {
                pwh = *reinterpret_cast<const uint4*>(Wh_g + (size_t)(n0 + br) * K2 + kp0 + bkp);
                pwl = *reinterpret_cast<const uint4*>(Wl_g + (size_t)(n0 + br) * K2 + kp0 + bkp);
            }
        }
        __syncthreads();

        const unsigned bAh = smem_u32(&sAh[buf][0]);
        const unsigned bAl = smem_u32(&sAl[buf][0]);
        const unsigned bWh = smem_u32(&sWh[buf][0]);
        const unsigned bWl = smem_u32(&sWl[buf][0]);

        unsigned Ah[2][4], Al[2][4], Bh[4][2], Bl[4][2];
        LDSM4(Ah[0][0], Ah[0][1], Ah[0][2], Ah[0][3], bAh + offA0);
        LDSM4(Ah[1][0], Ah[1][1], Ah[1][2], Ah[1][3], bAh + offA1);
        LDSM4(Al[0][0], Al[0][1], Al[0][2], Al[0][3], bAl + offA0);
        LDSM4(Al[1][0], Al[1][1], Al[1][2], Al[1][3], bAl + offA1);
        LDSM4(Bh[0][0], Bh[1][0], Bh[0][1], Bh[1][1], bWh + offB0);
        LDSM4(Bh[2][0], Bh[3][0], Bh[2][1], Bh[3][1], bWh + offB1);
        LDSM4(Bl[0][0], Bl[1][0], Bl[0][1], Bl[1][1], bWl + offB0);
        LDSM4(Bl[2][0], Bl[3][0], Bl[2][1], Bl[3][1], bWl + offB1);

#pragma unroll
        for (int mt = 0; mt < 2; mt++)
#pragma unroll
            for (int nt = 0; nt < 4; nt++) {
                MMA_BF16(cacc[mt][nt], Ah[mt], Bh[nt]);
                MMA_BF16(cacc[mt][nt], Ah[mt], Bl[nt]);
                MMA_BF16(cacc[mt][nt], Al[mt], Bh[nt]);
            }
    }

    // ---- epilogue ----
    const int N2 = N >> 1;
#pragma unroll
    for (int mt = 0; mt < 2; mt++) {
        int row0 = m0 + wm * 32 + mt * 16 + g;
#pragma unroll
        for (int nt = 0; nt < 4; nt++) {
            int col = n0 + wn * 32 + nt * 8 + 2 * tig;
            float b0 = bias[col], b1 = bias[col + 1];
            float v00 = cacc[mt][nt][0] + b0;
            float v01 = cacc[mt][nt][1] + b1;
            float v10 = cacc[mt][nt][2] + b0;
            float v11 = cacc[mt][nt][3] + b1;
            if (mode != 0) { v00 = siluf(v00); v01 = siluf(v01); v10 = siluf(v10); v11 = siluf(v11); }
            if (mode == 2) {
                unsigned hi, lo;
                split2(v00, v01, hi, lo);
                CH[(size_t)row0 * N2 + (col >> 1)] = hi;
                CL[(size_t)row0 * N2 + (col >> 1)] = lo;
                split2(v10, v11, hi, lo);
                CH[(size_t)(row0 + 8) * N2 + (col >> 1)] = hi;
                CL[(size_t)(row0 + 8) * N2 + (col >> 1)] = lo;
            } else {
                float2 r0 = {v00, v01};
                float2 r1 = {v10, v11};
                *reinterpret_cast<float2*>(Cf + (size_t)row0 * N + col) = r0;
                *reinterpret_cast<float2*>(Cf + (size_t)(row0 + 8) * N + col) = r1;
            }
        }
    }
}

// ---------------- k_contract: tpw(4608) x node tensors -> vec[pos][80] ---------
__global__ void __launch_bounds__(128)
k_contract(const float* __restrict__ h_full)
{
    __shared__ float s1[NODE_S];
    __shared__ float v1s[NODE_V * 3];
    __shared__ float bvi[NODE_V];
    __shared__ float uu[3];

    const int pos = blockIdx.x;
    if (pos >= g_count) return;
    const int tid = threadIdx.x;
    const int node = g_active[pos];
    const float* hf = h_full + (size_t)node * 160;

    if (tid < NODE_S) s1[tid] = hf[tid];
    if (tid < NODE_V * 3) v1s[tid] = hf[NODE_S + tid];
    if (tid < 3) uu[tid] = g_u[pos * 3 + tid];
    __syncthreads();
    if (tid < NODE_V)
        bvi[tid] = v1s[3 * tid] * uu[0] + v1s[3 * tid + 1] * uu[1] + v1s[3 * tid + 2] * uu[2];
    __syncthreads();

    const float* tp = g_tpw + (size_t)pos * WN;
    const float mul = g_mul[pos];

    if (tid < OUT_S) {
        int o = tid;
        float acc = 0.0f;
#pragma unroll 8
        for (int i = 0; i < NODE_S; i++) acc += s1[i] * tp[i * OUT_S + o];
#pragma unroll 8
        for (int i = 0; i < NODE_V; i++) acc += bvi[i] * tp[2048 + i * OUT_S + o];
        g_vec[(size_t)pos * OUT_DIM + o] = acc * mul;
    }
    if (tid >= 64 && tid < 112) {
        int t = tid - 64;
        int o = t & 15, c = t >> 4;      // o<16, c<3
        float sc = 0.0f, sd = 0.0f;
#pragma unroll 8
        for (int i = 0; i < NODE_S; i++) sc += s1[i] * tp[3072 + i * OUT_V + o];
#pragma unroll 8
        for (int i = 0; i < NODE_V; i++) sd += v1s[3 * i + c] * tp[4096 + i * OUT_V + o];
        float yv = SQRT3_F * uu[c];
        g_vec[(size_t)pos * OUT_DIM + OUT_S + o * 3 + c] = (sc * yv + sd) * mul;
    }
}

// ---------------- k_vabs1/2: deterministic per-batch reduce over active nodes ---
__global__ void k_vabs1() {
    int b = blockIdx.x, ch = blockIdx.y, t = threadIdx.x;
    if (t >= OUT_DIM) return;
    float acc = 0.0f;
    int nbase = b * NN + ch * 32;
    for (int n = 0; n < 32; n++) {
        int node = nbase + n;
        if (g_winner[node] >= 0)
            acc += g_vec[(size_t)g_posmap[node] * OUT_DIM + t];
    }
    g_vpart[(b * 4 + ch) * OUT_DIM + t] = acc;
}
__global__ void k_vabs2() {
    int b = blockIdx.x, t = threadIdx.x;
    if (t >= OUT_DIM) return;
    float acc = 0.0f;
#pragma unroll
    for (int ch = 0; ch < 4; ch++)
        acc += g_vpart[(b * 4 + ch) * OUT_DIM + t];
    g_vabs[b * OUT_DIM + t] = acc;
}

// ---------------- k_invs: build invariants, write split bf16 hi/lo directly ------
__global__ void __launch_bounds__(256)
k_invs()
{
    int t = blockIdx.x * blockDim.x + threadIdx.x;
    if (t >= ROWS3 * 24) return;
    int row = t / 24, jp = t - row * 24;
    int b = row >> 9, e = row & 511;
    float vals[2];
#pragma unroll
    for (int jj = 0; jj < 2; jj++) {
        int j = 2 * jp + jj;
        float v;
        if (j < OUT_S) {
            v = g_vabs[b * OUT_DIM + j] * g_scales[e * 48 + j];
        } else {
            int o = j - OUT_S;
            float s = g_scales[e * 48 + OUT_S + o];
            float x0 = g_vabs[b * OUT_DIM + OUT_S + o * 3 + 0] * s;
            float x1 = g_vabs[b * OUT_DIM + OUT_S + o * 3 + 1] * s;
            float x2 = g_vabs[b * OUT_DIM + OUT_S + o * 3 + 2] * s;
            v = sqrtf(x0 * x0 + x1 * x1 + x2 * x2 + 1e-12f);
        }
        vals[jj] = v;
    }
    unsigned hi, lo;
    split2(vals[0], vals[1], hi, lo);
    g_invH[row * 24 + jp] = hi;
    g_invL[row * 24 + jp] = lo;
}

// ---------------- launch ----------------
extern "C" void kernel_launch(void* const* d_in, const int* in_sizes, int n_in,
                              void* d_out, int out_size)
{
    const float* h        = (const float*)d_in[0];
    const float* h_full   = (const float*)d_in[1];
    const int*   z        = (const int*)  d_in[2];
    const float* e_feat   = (const float*)d_in[4];
    const int*   abs_idx  = (const int*)  d_in[5];
    const int*   att_dst  = (const int*)  d_in[6];
    const float* att_dist = (const float*)d_in[7];
    const float* att_vec  = (const float*)d_in[8];
    const float* w_zemb   = (const float*)d_in[9];
    const float* w1_rad   = (const float*)d_in[10];
    const float* b1_rad   = (const float*)d_in[11];
    const float* w2_rad   = (const float*)d_in[12];
    const float* b2_rad   = (const float*)d_in[13];
    const float* wg1      = (const float*)d_in[14];
    const float* bg1      = (const float*)d_in[15];
    const float* wg2      = (const float*)d_in[16];
    const float* bg2      = (const float*)d_in[17];
    const float* we1      = (const float*)d_in[18];
    const float* be1      = (const float*)d_in[19];
    const float* we2      = (const float*)d_in[20];
    const float* be2      = (const float*)d_in[21];
    const float* wo1      = (const float*)d_in[22];
    const float* bo1      = (const float*)d_in[23];
    const float* wo2      = (const float*)d_in[24];
    const float* bo2      = (const float*)d_in[25];
    const float* wo3      = (const float*)d_in[26];
    const float* bo3      = (const float*)d_in[27];
    float* out = (float*)d_out;

    float *d_ghid, *d_tpw;
    unsigned *d_winH, *d_winL, *d_ginH, *d_ginL, *d_hidH, *d_hidL;
    unsigned *d_invH, *d_invL, *d_x1H, *d_x1L, *d_x2H, *d_x2L;
    unsigned *d_wg1H, *d_wg1L, *d_w1H, *d_w1L, *d_w2H, *d_w2L;
    unsigned *d_wo1H, *d_wo1L, *d_wo2H, *d_wo2L, *d_wo3H, *d_wo3L;
    cudaGetSymbolAddress((void**)&d_ghid, g_ghid);
    cudaGetSymbolAddress((void**)&d_tpw,  g_tpw);
    cudaGetSymbolAddress((void**)&d_winH, g_winH);
    cudaGetSymbolAddress((void**)&d_winL, g_winL);
    cudaGetSymbolAddress((void**)&d_ginH, g_ginH);
    cudaGetSymbolAddress((void**)&d_ginL, g_ginL);
    cudaGetSymbolAddress((void**)&d_hidH, g_hidH);
    cudaGetSymbolAddress((void**)&d_hidL, g_hidL);
    cudaGetSymbolAddress((void**)&d_invH, g_invH);
    cudaGetSymbolAddress((void**)&d_invL, g_invL);
    cudaGetSymbolAddress((void**)&d_x1H,  g_x1H);
    cudaGetSymbolAddress((void**)&d_x1L,  g_x1L);
    cudaGetSymbolAddress((void**)&d_x2H,  g_x2H);
    cudaGetSymbolAddress((void**)&d_x2L,  g_x2L);
    cudaGetSymbolAddress((void**)&d_wg1H, g_wg1H);
    cudaGetSymbolAddress((void**)&d_wg1L, g_wg1L);
    cudaGetSymbolAddress((void**)&d_w1H,  g_w1H);
    cudaGetSymbolAddress((void**)&d_w1L,  g_w1L);
    cudaGetSymbolAddress((void**)&d_w2H,  g_w2H);
    cudaGetSymbolAddress((void**)&d_w2L,  g_w2L);
    cudaGetSymbolAddress((void**)&d_wo1H, g_wo1H);
    cudaGetSymbolAddress((void**)&d_wo1L, g_wo1L);
    cudaGetSymbolAddress((void**)&d_wo2H, g_wo2H);
    cudaGetSymbolAddress((void**)&d_wo2L, g_wo2L);
    cudaGetSymbolAddress((void**)&d_wo3H, g_wo3H);
    cudaGetSymbolAddress((void**)&d_wo3L, g_wo3L);

    k_initw<<<(SEG5 + 255) / 256, 256>>>(wg1, w1_rad, w2_rad, wo1, wo2, wo3);
    k_scatter<<<(EATT_N + 255) / 256, 256>>>(att_dst);
    k_compact<<<(FLAT + 255) / 256, 256>>>();
    k_prep<<<NACT_MAX + NEE, 128>>>(h, z, abs_idx, att_dist, att_vec, w_zemb,
                                    e_feat, we1, be1, we2, be2);

    // gate hidden = silu(gin @ wg1 + bg1): 4096 x 128, K=288 -> f32
    k_bmma<<<dim3(2, NACT_MAX / 128), 256>>>(d_ginH, d_ginL, d_wg1H, d_wg1L, bg1,
                                             d_ghid, nullptr, nullptr, NACT_MAX, 128, KGIN, 1);
    // rad hidden = silu(win @ w1 + b1): 4096 x 128, K=64 -> split
    k_bmma<<<dim3(2, NACT_MAX / 128), 256>>>(d_winH, d_winL, d_w1H, d_w1L, b1_rad,
                                             nullptr, d_hidH, d_hidL, NACT_MAX, 128, KWIN, 2);
    k_gate2<<<NACT_MAX / 8, 256>>>(wg2, bg2);

    // tpw = hid @ w2 + b2: 4096 x 4608, K=128 -> f32
    k_bmma<<<dim3(WN / 64, NACT_MAX / 128), 256>>>(d_hidH, d_hidL, d_w2H, d_w2L, b2_rad,
                                                   d_tpw, nullptr, nullptr, NACT_MAX, WN, HIDN, 0);
    k_contract<<<NACT_MAX, 128>>>(h_full);
    k_vabs1<<<dim3(BB, 4), 80>>>();
    k_vabs2<<<BB, 80>>>();
    k_invs<<<(ROWS3 * 24 + 255) / 256, 256>>>();

    // tail MLP
    k_bmma<<<dim3(2, ROWS3 / 128), 256>>>(d_invH, d_invL, d_wo1H, d_wo1L, bo1,
                                          nullptr, d_x1H, d_x1L, ROWS3, 128, 48, 2);
    k_bmma<<<dim3(2, ROWS3 / 128), 256>>>(d_x1H, d_x1L, d_wo2H, d_wo2L, bo2,
                                          nullptr, d_x2H, d_x2L, ROWS3, 128, HIDN, 2);
    k_bmma<<<dim3(4, ROWS3 / 128), 256>>>(d_x2H, d_x2L, d_wo3H, d_wo3L, bo3,
                                          out, nullptr, nullptr, ROWS3, 256, HIDN, 0);
}

// round 13
// speedup vs baseline: 1.0183x; 1.0183x over previous
#include <cuda_runtime.h>
#include <cuda_bf16.h>
#include <math.h>
#include <stdint.h>

// ---------------- problem constants ----------------
#define BB        64
#define NN        128
#define FLAT      8192          // B*N
#define H_DIM     128
#define NODE_S    64
#define NODE_V    32
#define OUT_S     32
#define OUT_V     16
#define OUT_DIM   80
#define HIDN      128
#define NEE       512
#define EATT_N    4096
#define WN        4608
#define CUTOFF_F  5.0f
#define NORM_F    0.10206207261596575f   // 1/sqrt(96)
#define SQRT3_F   1.7320508075688772f
#define NACT_MAX  4096
#define ROWS3     32768         // B * NE
#define KWIN      64            // padded 49
#define KGIN      288           // padded 273

// ---------------- scratch (static device memory) ----------------
// g_winner holds edge+1 (0 = inactive). Statically zero-initialized; reset to 0
// at the END of each replay (tail of k_invs) so the graph is idempotent.
__device__ int   g_winner[FLAT];
__device__ int   g_active[FLAT];
__device__ int   g_posmap[FLAT];
__device__ int   g_count;
__device__ float g_ghid  [NACT_MAX * HIDN];
__device__ float g_env   [NACT_MAX];
__device__ float g_mul   [NACT_MAX];
__device__ float g_u     [NACT_MAX * 3];
__device__ float g_tpw   [NACT_MAX * WN];     // 75.5 MB
__device__ float g_vec   [NACT_MAX * OUT_DIM];
__device__ float g_vpart [BB * 4 * OUT_DIM];
__device__ float g_scales[NEE * 48];

// pre-split bf16 hi/lo packed operands (u32 = bf16x2 over consecutive k)
// activations: [row][K/2];  weights: [n][K/2] (transposed at split time)
__device__ __align__(16) unsigned g_winH[NACT_MAX * (KWIN/2)];
__device__ __align__(16) unsigned g_winL[NACT_MAX * (KWIN/2)];
__device__ __align__(16) unsigned g_ginH[NACT_MAX * (KGIN/2)];
__device__ __align__(16) unsigned g_ginL[NACT_MAX * (KGIN/2)];
__device__ __align__(16) unsigned g_hidH[NACT_MAX * (HIDN/2)];
__device__ __align__(16) unsigned g_hidL[NACT_MAX * (HIDN/2)];
__device__ __align__(16) unsigned g_invH[ROWS3 * 24];
__device__ __align__(16) unsigned g_invL[ROWS3 * 24];
__device__ __align__(16) unsigned g_x1H[ROWS3 * 64];
__device__ __align__(16) unsigned g_x1L[ROWS3 * 64];
__device__ __align__(16) unsigned g_x2H[ROWS3 * 64];
__device__ __align__(16) unsigned g_x2L[ROWS3 * 64];
__device__ __align__(16) unsigned g_wg1H[128 * 144];
__device__ __align__(16) unsigned g_wg1L[128 * 144];
__device__ __align__(16) unsigned g_w1H[128 * 32];
__device__ __align__(16) unsigned g_w1L[128 * 32];
__device__ __align__(16) unsigned g_w2H[4608 * 64];
__device__ __align__(16) unsigned g_w2L[4608 * 64];
__device__ __align__(16) unsigned g_wo1H[128 * 24];
__device__ __align__(16) unsigned g_wo1L[128 * 24];
__device__ __align__(16) unsigned g_wo2H[128 * 64];
__device__ __align__(16) unsigned g_wo2L[128 * 64];
__device__ __align__(16) unsigned g_wo3H[256 * 64];
__device__ __align__(16) unsigned g_wo3L[256 * 64];

__device__ __forceinline__ float siluf(float x) { return x / (1.0f + expf(-x)); }
__device__ __forceinline__ float sigmoidf_(float x) { return 1.0f / (1.0f + expf(-x)); }

__device__ __forceinline__ unsigned smem_u32(const void* p) {
    return (unsigned)__cvta_generic_to_shared(p);
}

// split a pair of fp32 into hi/lo bf16x2 packed words (low half = first elem)
__device__ __forceinline__ void split2(float x, float y, unsigned& hi, unsigned& lo) {
    __nv_bfloat162 hh = __floats2bfloat162_rn(x, y);
    float hx = __bfloat162float(__low2bfloat16(hh));
    float hy = __bfloat162float(__high2bfloat16(hh));
    __nv_bfloat162 ll = __floats2bfloat162_rn(x - hx, y - hy);
    hi = *reinterpret_cast<unsigned*>(&hh);
    lo = *reinterpret_cast<unsigned*>(&ll);
}

#define MMA_BF16(c, a, b)                                                        \
    asm volatile(                                                                \
        "mma.sync.aligned.m16n8k16.row.col.f32.bf16.bf16.f32 "                   \
        "{%0,%1,%2,%3},{%4,%5,%6,%7},{%8,%9},{%0,%1,%2,%3};"                     \
        : "+f"((c)[0]), "+f"((c)[1]), "+f"((c)[2]), "+f"((c)[3])                 \
        : "r"((a)[0]), "r"((a)[1]), "r"((a)[2]), "r"((a)[3]),                    \
          "r"((b)[0]), "r"((b)[1]))

#define LDSM4(R0, R1, R2, R3, ADDR)                                              \
    asm volatile(                                                                \
        "ldmatrix.sync.aligned.m8n8.x4.shared.b16 {%0,%1,%2,%3}, [%4];"          \
        : "=r"(R0), "=r"(R1), "=r"(R2), "=r"(R3) : "r"(ADDR))

// ---------------- k_initw: edge scatter + weight pre-split (merged) ------------
// weight split output layout: [n][K/2] u32 (pair over k). segments:
// wg1(128n x 144) w1(128 x 32) w2(4608 x 64) wo1(128 x 24) wo2(128 x 64) wo3(256 x 64)
#define SEG0 18432
#define SEG1 22528
#define SEG2 317440
#define SEG3 320512
#define SEG4 328704
#define SEG5 345088
__global__ void k_initw(const int* __restrict__ att_dst,
                        const float* __restrict__ wg1, const float* __restrict__ w1,
                        const float* __restrict__ w2,  const float* __restrict__ wo1,
                        const float* __restrict__ wo2, const float* __restrict__ wo3)
{
    int i = blockIdx.x * blockDim.x + threadIdx.x;
    if (i < EATT_N) atomicMax(&g_winner[att_dst[i]], i + 1);   // last-write-wins
    if (i >= SEG5) return;
    const float* src; unsigned *H, *L; int Nn, K2, Kreal, li;
    if (i < SEG0)      { src = wg1; H = g_wg1H; L = g_wg1L; Nn = 128;  K2 = 144; Kreal = 273; li = i; }
    else if (i < SEG1) { src = w1;  H = g_w1H;  L = g_w1L;  Nn = 128;  K2 = 32;  Kreal = 49;  li = i - SEG0; }
    else if (i < SEG2) { src = w2;  H = g_w2H;  L = g_w2L;  Nn = 4608; K2 = 64;  Kreal = 128; li = i - SEG1; }
    else if (i < SEG3) { src = wo1; H = g_wo1H; L = g_wo1L; Nn = 128;  K2 = 24;  Kreal = 48;  li = i - SEG2; }
    else if (i < SEG4) { src = wo2; H = g_wo2H; L = g_wo2L; Nn = 128;  K2 = 64;  Kreal = 128; li = i - SEG3; }
    else               { src = wo3; H = g_wo3H; L = g_wo3L; Nn = 256;  K2 = 64;  Kreal = 128; li = i - SEG4; }
    int n = li / K2, kp = li - n * K2;
    int k0 = 2 * kp;
    float x = (k0 < Kreal)     ? src[(size_t)k0 * Nn + n]       : 0.0f;
    float y = (k0 + 1 < Kreal) ? src[(size_t)(k0 + 1) * Nn + n] : 0.0f;
    unsigned hi, lo;
    split2(x, y, hi, lo);
    H[li] = hi; L[li] = lo;
}

__global__ void k_compact() {
    int i = blockIdx.x * blockDim.x + threadIdx.x;
    if (i < FLAT && g_winner[i] > 0) {
        int p = atomicAdd(&g_count, 1);
        g_active[p] = i;
        g_posmap[i] = p;
    }
}

// ---------------- k_prep: split input rows per active node (+scales merged) ----
__global__ void __launch_bounds__(128)
k_prep(const float* __restrict__ h,
       const int*   __restrict__ z,
       const int*   __restrict__ absorber_index,
       const float* __restrict__ att_dist,
       const float* __restrict__ att_vec,
       const float* __restrict__ w_zemb,
       const float* __restrict__ e_feat,
       const float* __restrict__ we1, const float* __restrict__ be1,
       const float* __restrict__ we2, const float* __restrict__ be2)
{
    const int tid = threadIdx.x;
    if (blockIdx.x >= NACT_MAX) {
        __shared__ float hidd[HIDN];
        int e = blockIdx.x - NACT_MAX;
        float acc = be1[tid];
        for (int k = 0; k < 16; k++) acc += e_feat[e * 16 + k] * we1[k * HIDN + tid];
        hidd[tid] = siluf(acc);
        __syncthreads();
        if (tid < 48) {
            float s = be2[tid];
            for (int k = 0; k < HIDN; k++) s += hidd[k] * we2[k * 48 + tid];
            g_scales[e * 48 + tid] = s;
        }
        return;
    }
    const int pos = blockIdx.x;
    if (pos >= g_count) return;
    const int node = g_active[pos];
    const int b = node >> 7, n = node & 127;
    const int e = g_winner[node] - 1;
    const float d = att_dist[e];
    const int absb = absorber_index[b];
    const float isabs = (n == absb) ? 1.0f : 0.0f;
    const float width = CUTOFF_F / 15.0f;
    const float invwidth = 15.0f / CUTOFF_F;
    unsigned hi, lo;

    if (tid < KWIN) {
        float v = 0.0f;
        if (tid < 32)       v = w_zemb[z[node] * 32 + tid];
        else if (tid == 32) v = isabs;
        else if (tid < 49) {
            float t = (d - (float)(tid - 33) * width) * invwidth;
            v = expf(-0.5f * t * t);
        }
        float vp = __shfl_xor_sync(0xffffffffu, v, 1);
        if (!(tid & 1)) {
            split2(v, vp, hi, lo);
            g_winH[pos * 32 + (tid >> 1)] = hi;
            g_winL[pos * 32 + (tid >> 1)] = lo;
        }
    }
    {
        float v = h[(b * NN + absb) * H_DIM + tid];
        float vp = __shfl_xor_sync(0xffffffffu, v, 1);
        if (!(tid & 1)) {
            split2(v, vp, hi, lo);
            g_ginH[pos * 144 + (tid >> 1)] = hi;
            g_ginL[pos * 144 + (tid >> 1)] = lo;
        }
    }
    {
        float v = h[node * H_DIM + tid];
        float vp = __shfl_xor_sync(0xffffffffu, v, 1);
        if (!(tid & 1)) {
            split2(v, vp, hi, lo);
            g_ginH[pos * 144 + 64 + (tid >> 1)] = hi;
            g_ginL[pos * 144 + 64 + (tid >> 1)] = lo;
        }
    }
    if (tid < 32) {
        float v = 0.0f;
        if (tid < 16) {
            float t = (d - (float)tid * width) * invwidth;
            v = expf(-0.5f * t * t);
        } else if (tid == 16) v = isabs;
        float vp = __shfl_xor_sync(0xffffffffu, v, 1);
        if (!(tid & 1)) {
            split2(v, vp, hi, lo);
            g_ginH[pos * 144 + 128 + (tid >> 1)] = hi;
            g_ginL[pos * 144 + 128 + (tid >> 1)] = lo;
        }
    }
    if (tid == 0)
        g_env[pos] = (d < CUTOFF_F) ? 0.5f * (cospif(d / CUTOFF_F) + 1.0f) : 0.0f;
    if (tid < 3)
        g_u[pos * 3 + tid] = att_vec[e * 3 + tid] / fmaxf(d, 1e-8f);
}

// ---------------- k_gate2 ----------------
__global__ void __launch_bounds__(256)
k_gate2(const float* __restrict__ wg2, const float* __restrict__ bg2)
{
    int wid = threadIdx.x >> 5, lane = threadIdx.x & 31;
    int pos = blockIdx.x * 8 + wid;
    if (pos >= g_count) return;
    float s = 0.0f;
#pragma unroll
    for (int j = 0; j < 4; j++) {
        int k = lane + 32 * j;
        s += g_ghid[pos * HIDN + k] * wg2[k];
    }
#pragma unroll
    for (int off = 16; off > 0; off >>= 1) s += __shfl_xor_sync(0xffffffffu, s, off);
    if (lane == 0)
        g_mul[pos] = sigmoidf_(s + bg2[0]) * g_env[pos] * NORM_F;
}

// ================= split-bf16 tensor-core GEMM (ldmatrix fragments) ============
// C = act(A @ W + bias). Block tile 128x64, BK=16, 256 threads, 8 warps 4x2,
// warp tile 32x32 via m16n8k16. D = AhBh + AhBl + AlBh.
// A: [M][K/2] u32;  W: [n][K/2] u32 (weight pre-transposed at split).
// smem: both tiles row-major [row][kpair] with stride 12 u32 (48B) --
// rows hit distinct 16B banks, so ldmatrix and uint4 staging are conflict-free.
// Double-buffered, 1 sync/k16.
// mode: 0 = f32 out, 1 = f32 + silu, 2 = split(hi/lo) + silu.
__global__ void __launch_bounds__(256, 2)
k_bmma(const unsigned* __restrict__ Ah_g, const unsigned* __restrict__ Al_g,
       const unsigned* __restrict__ Wh_g, const unsigned* __restrict__ Wl_g,
       const float* __restrict__ bias,
       float* __restrict__ Cf, unsigned* __restrict__ CH, unsigned* __restrict__ CL,
       int M, int N, int K, int mode)
{
    __shared__ __align__(16) unsigned sAh[2][128 * 12];
    __shared__ __align__(16) unsigned sAl[2][128 * 12];
    __shared__ __align__(16) unsigned sWh[2][64 * 12];
    __shared__ __align__(16) unsigned sWl[2][64 * 12];

    const int tid = threadIdx.x;
    const int wid = tid >> 5, lane = tid & 31;
    const int wm = wid & 3, wn = wid >> 2;
    const int g = lane >> 2, tig = lane & 3;
    const int m0 = blockIdx.y * 128, n0 = blockIdx.x * 64;
    const int K2 = K >> 1;
    const int nk = K >> 4;

    const int ar = tid >> 1, akp = (tid & 1) * 4;
    const int br = tid & 63, bkp = ((tid >> 6) & 1) * 4;

    const int sel = lane >> 3;
    const int lrow = (lane & 7) + (sel & 1) * 8;
    const int lcol = (sel >> 1) * 4;
    const unsigned offA0 = ((wm * 32 + lrow) * 12 + lcol) * 4;
    const unsigned offA1 = ((wm * 32 + 16 + lrow) * 12 + lcol) * 4;
    const unsigned offB0 = ((wn * 32 + lrow) * 12 + lcol) * 4;
    const unsigned offB1 = ((wn * 32 + 16 + lrow) * 12 + lcol) * 4;

    float cacc[2][4][4];
#pragma unroll
    for (int mt = 0; mt < 2; mt++)
#pragma unroll
        for (int nt = 0; nt < 4; nt++)
#pragma unroll
            for (int i = 0; i < 4; i++) cacc[mt][nt][i] = 0.0f;

    uint4 pah = *reinterpret_cast<const uint4*>(Ah_g + (size_t)(m0 + ar) * K2 + akp);
    uint4 pal = *reinterpret_cast<const uint4*>(Al_g + (size_t)(m0 + ar) * K2 + akp);
    uint4 pwh = make_uint4(0, 0, 0, 0), pwl = make_uint4(0, 0, 0, 0);
    if (tid < 128) {
        pwh = *reinterpret_cast<const uint4*>(Wh_g + (size_t)(n0 + br) * K2 + bkp);
        pwl = *reinterpret_cast<const uint4*>(Wl_g + (size_t)(n0 + br) * K2 + bkp);
    }

    for (int it = 0; it < nk; it++) {
        const int buf = it & 1;
        *reinterpret_cast<uint4*>(&sAh[buf][ar * 12 + akp]) = pah;
        *reinterpret_cast<uint4*>(&sAl[buf][ar * 12 + akp]) = pal;
        if (tid < 128) {
            *reinterpret_cast<uint4*>(&sWh[buf][br * 12 + bkp]) = pwh;
            *reinterpret_cast<uint4*>(&sWl[buf][br * 12 + bkp]) = pwl;
        }
        if (it + 1 < nk) {
            int kp0 = (it + 1) * 8;
            pah = *reinterpret_cast<const uint4*>(Ah_g + (size_t)(m0 + ar) * K2 + kp0 + akp);
            pal = *reinterpret_cast<const uint4*>(Al_g + (size_t)(m0 + ar) * K2 + kp0 + akp);
            if (tid < 128) {
                pwh = *reinterpret_cast<const uint4*>(Wh_g + (size_t)(n0 + br) * K2 + kp0 + bkp);
                pwl = *reinterpret_cast<const uint4*>(Wl_g + (size_t)(n0 + br) * K2 + kp0 + bkp);
            }
        }
        __syncthreads();

        const unsigned bAh = smem_u32(&sAh[buf][0]);
        const unsigned bAl = smem_u32(&sAl[buf][0]);
        const unsigned bWh = smem_u32(&sWh[buf][0]);
        const unsigned bWl = smem_u32(&sWl[buf][0]);

        unsigned Ah[2][4], Al[2][4], Bh[4][2], Bl[4][2];
        LDSM4(Ah[0][0], Ah[0][1], Ah[0][2], Ah[0][3], bAh + offA0);
        LDSM4(Ah[1][0], Ah[1][1], Ah[1][2], Ah[1][3], bAh + offA1);
        LDSM4(Al[0][0], Al[0][1], Al[0][2], Al[0][3], bAl + offA0);
        LDSM4(Al[1][0], Al[1][1], Al[1][2], Al[1][3], bAl + offA1);
        LDSM4(Bh[0][0], Bh[1][0], Bh[0][1], Bh[1][1], bWh + offB0);
        LDSM4(Bh[2][0], Bh[3][0], Bh[2][1], Bh[3][1], bWh + offB1);
        LDSM4(Bl[0][0], Bl[1][0], Bl[0][1], Bl[1][1], bWl + offB0);
        LDSM4(Bl[2][0], Bl[3][0], Bl[2][1], Bl[3][1], bWl + offB1);

#pragma unroll
        for (int mt = 0; mt < 2; mt++)
#pragma unroll
            for (int nt = 0; nt < 4; nt++) {
                MMA_BF16(cacc[mt][nt], Ah[mt], Bh[nt]);
                MMA_BF16(cacc[mt][nt], Ah[mt], Bl[nt]);
                MMA_BF16(cacc[mt][nt], Al[mt], Bh[nt]);
            }
    }

    // ---- epilogue ----
    const int N2 = N >> 1;
#pragma unroll
    for (int mt = 0; mt < 2; mt++) {
        int row0 = m0 + wm * 32 + mt * 16 + g;
#pragma unroll
        for (int nt = 0; nt < 4; nt++) {
            int col = n0 + wn * 32 + nt * 8 + 2 * tig;
            float b0 = bias[col], b1 = bias[col + 1];
            float v00 = cacc[mt][nt][0] + b0;
            float v01 = cacc[mt][nt][1] + b1;
            float v10 = cacc[mt][nt][2] + b0;
            float v11 = cacc[mt][nt][3] + b1;
            if (mode != 0) { v00 = siluf(v00); v01 = siluf(v01); v10 = siluf(v10); v11 = siluf(v11); }
            if (mode == 2) {
                unsigned hi, lo;
                split2(v00, v01, hi, lo);
                CH[(size_t)row0 * N2 + (col >> 1)] = hi;
                CL[(size_t)row0 * N2 + (col >> 1)] = lo;
                split2(v10, v11, hi, lo);
                CH[(size_t)(row0 + 8) * N2 + (col >> 1)] = hi;
                CL[(size_t)(row0 + 8) * N2 + (col >> 1)] = lo;
            } else {
                float2 r0 = {v00, v01};
                float2 r1 = {v10, v11};
                *reinterpret_cast<float2*>(Cf + (size_t)row0 * N + col) = r0;
                *reinterpret_cast<float2*>(Cf + (size_t)(row0 + 8) * N + col) = r1;
            }
        }
    }
}

// ---------------- k_contract: tpw(4608) x node tensors -> vec[pos][80] ---------
__global__ void __launch_bounds__(128)
k_contract(const float* __restrict__ h_full)
{
    __shared__ float s1[NODE_S];
    __shared__ float v1s[NODE_V * 3];
    __shared__ float bvi[NODE_V];
    __shared__ float uu[3];

    const int pos = blockIdx.x;
    if (pos >= g_count) return;
    const int tid = threadIdx.x;
    const int node = g_active[pos];
    const float* hf = h_full + (size_t)node * 160;

    if (tid < NODE_S) s1[tid] = hf[tid];
    if (tid < NODE_V * 3) v1s[tid] = hf[NODE_S + tid];
    if (tid < 3) uu[tid] = g_u[pos * 3 + tid];
    __syncthreads();
    if (tid < NODE_V)
        bvi[tid] = v1s[3 * tid] * uu[0] + v1s[3 * tid + 1] * uu[1] + v1s[3 * tid + 2] * uu[2];
    __syncthreads();

    const float* tp = g_tpw + (size_t)pos * WN;
    const float mul = g_mul[pos];

    if (tid < OUT_S) {
        int o = tid;
        float acc = 0.0f;
#pragma unroll 8
        for (int i = 0; i < NODE_S; i++) acc += s1[i] * tp[i * OUT_S + o];
#pragma unroll 8
        for (int i = 0; i < NODE_V; i++) acc += bvi[i] * tp[2048 + i * OUT_S + o];
        g_vec[(size_t)pos * OUT_DIM + o] = acc * mul;
    }
    if (tid >= 64 && tid < 112) {
        int t = tid - 64;
        int o = t & 15, c = t >> 4;      // o<16, c<3
        float sc = 0.0f, sd = 0.0f;
#pragma unroll 8
        for (int i = 0; i < NODE_S; i++) sc += s1[i] * tp[3072 + i * OUT_V + o];
#pragma unroll 8
        for (int i = 0; i < NODE_V; i++) sd += v1s[3 * i + c] * tp[4096 + i * OUT_V + o];
        float yv = SQRT3_F * uu[c];
        g_vec[(size_t)pos * OUT_DIM + OUT_S + o * 3 + c] = (sc * yv + sd) * mul;
    }
}

// ---------------- k_vabs1: deterministic per-batch partial reduce ---------------
__global__ void k_vabs1() {
    int b = blockIdx.x, ch = blockIdx.y, t = threadIdx.x;
    if (t >= OUT_DIM) return;
    float acc = 0.0f;
    int nbase = b * NN + ch * 32;
    for (int n = 0; n < 32; n++) {
        int node = nbase + n;
        if (g_winner[node] > 0)
            acc += g_vec[(size_t)g_posmap[node] * OUT_DIM + t];
    }
    g_vpart[(b * 4 + ch) * OUT_DIM + t] = acc;
}

// ---------------- k_invs: invariants (split bf16) + end-of-replay reset --------
__device__ __forceinline__ float vabs_of(int b, int j) {
    float a = g_vpart[(b * 4 + 0) * OUT_DIM + j];
    a += g_vpart[(b * 4 + 1) * OUT_DIM + j];
    a += g_vpart[(b * 4 + 2) * OUT_DIM + j];
    a += g_vpart[(b * 4 + 3) * OUT_DIM + j];
    return a;
}

__global__ void __launch_bounds__(256)
k_invs()
{
    int t = blockIdx.x * blockDim.x + threadIdx.x;
    // end-of-replay reset: winner back to 0, count back to 0 (graph idempotence)
    if (t < FLAT) g_winner[t] = 0;
    if (t == 0)   g_count = 0;
    if (t >= ROWS3 * 24) return;
    int row = t / 24, jp = t - row * 24;
    int b = row >> 9, e = row & 511;
    float vals[2];
#pragma unroll
    for (int jj = 0; jj < 2; jj++) {
        int j = 2 * jp + jj;
        float v;
        if (j < OUT_S) {
            v = vabs_of(b, j) * g_scales[e * 48 + j];
        } else {
            int o = j - OUT_S;
            float s = g_scales[e * 48 + OUT_S + o];
            float x0 = vabs_of(b, OUT_S + o * 3 + 0) * s;
            float x1 = vabs_of(b, OUT_S + o * 3 + 1) * s;
            float x2 = vabs_of(b, OUT_S + o * 3 + 2) * s;
            v = sqrtf(x0 * x0 + x1 * x1 + x2 * x2 + 1e-12f);
        }
        vals[jj] = v;
    }
    unsigned hi, lo;
    split2(vals[0], vals[1], hi, lo);
    g_invH[row * 24 + jp] = hi;
    g_invL[row * 24 + jp] = lo;
}

// ---------------- launch ----------------
extern "C" void kernel_launch(void* const* d_in, const int* in_sizes, int n_in,
                              void* d_out, int out_size)
{
    const float* h        = (const float*)d_in[0];
    const float* h_full   = (const float*)d_in[1];
    const int*   z        = (const int*)  d_in[2];
    const float* e_feat   = (const float*)d_in[4];
    const int*   abs_idx  = (const int*)  d_in[5];
    const int*   att_dst  = (const int*)  d_in[6];
    const float* att_dist = (const float*)d_in[7];
    const float* att_vec  = (const float*)d_in[8];
    const float* w_zemb   = (const float*)d_in[9];
    const float* w1_rad   = (const float*)d_in[10];
    const float* b1_rad   = (const float*)d_in[11];
    const float* w2_rad   = (const float*)d_in[12];
    const float* b2_rad   = (const float*)d_in[13];
    const float* wg1      = (const float*)d_in[14];
    const float* bg1      = (const float*)d_in[15];
    const float* wg2      = (const float*)d_in[16];
    const float* bg2      = (const float*)d_in[17];
    const float* we1      = (const float*)d_in[18];
    const float* be1      = (const float*)d_in[19];
    const float* we2      = (const float*)d_in[20];
    const float* be2      = (const float*)d_in[21];
    const float* wo1      = (const float*)d_in[22];
    const float* bo1      = (const float*)d_in[23];
    const float* wo2      = (const float*)d_in[24];
    const float* bo2      = (const float*)d_in[25];
    const float* wo3      = (const float*)d_in[26];
    const float* bo3      = (const float*)d_in[27];
    float* out = (float*)d_out;

    float *d_ghid, *d_tpw;
    unsigned *d_winH, *d_winL, *d_ginH, *d_ginL, *d_hidH, *d_hidL;
    unsigned *d_invH, *d_invL, *d_x1H, *d_x1L, *d_x2H, *d_x2L;
    unsigned *d_wg1H, *d_wg1L, *d_w1H, *d_w1L, *d_w2H, *d_w2L;
    unsigned *d_wo1H, *d_wo1L, *d_wo2H, *d_wo2L, *d_wo3H, *d_wo3L;
    cudaGetSymbolAddress((void**)&d_ghid, g_ghid);
    cudaGetSymbolAddress((void**)&d_tpw,  g_tpw);
    cudaGetSymbolAddress((void**)&d_winH, g_winH);
    cudaGetSymbolAddress((void**)&d_winL, g_winL);
    cudaGetSymbolAddress((void**)&d_ginH, g_ginH);
    cudaGetSymbolAddress((void**)&d_ginL, g_ginL);
    cudaGetSymbolAddress((void**)&d_hidH, g_hidH);
    cudaGetSymbolAddress((void**)&d_hidL, g_hidL);
    cudaGetSymbolAddress((void**)&d_invH, g_invH);
    cudaGetSymbolAddress((void**)&d_invL, g_invL);
    cudaGetSymbolAddress((void**)&d_x1H,  g_x1H);
    cudaGetSymbolAddress((void**)&d_x1L,  g_x1L);
    cudaGetSymbolAddress((void**)&d_x2H,  g_x2H);
    cudaGetSymbolAddress((void**)&d_x2L,  g_x2L);
    cudaGetSymbolAddress((void**)&d_wg1H, g_wg1H);
    cudaGetSymbolAddress((void**)&d_wg1L, g_wg1L);
    cudaGetSymbolAddress((void**)&d_w1H,  g_w1H);
    cudaGetSymbolAddress((void**)&d_w1L,  g_w1L);
    cudaGetSymbolAddress((void**)&d_w2H,  g_w2H);
    cudaGetSymbolAddress((void**)&d_w2L,  g_w2L);
    cudaGetSymbolAddress((void**)&d_wo1H, g_wo1H);
    cudaGetSymbolAddress((void**)&d_wo1L, g_wo1L);
    cudaGetSymbolAddress((void**)&d_wo2H, g_wo2H);
    cudaGetSymbolAddress((void**)&d_wo2L, g_wo2L);
    cudaGetSymbolAddress((void**)&d_wo3H, g_wo3H);
    cudaGetSymbolAddress((void**)&d_wo3L, g_wo3L);

    // 1: edge scatter + weight split (winner is 0-initialized / reset by k_invs)
    k_initw<<<(SEG5 + 255) / 256, 256>>>(att_dst, wg1, w1_rad, w2_rad, wo1, wo2, wo3);
    // 2: compact active nodes
    k_compact<<<(FLAT + 255) / 256, 256>>>();
    // 3: per-node input prep + scales MLP
    k_prep<<<NACT_MAX + NEE, 128>>>(h, z, abs_idx, att_dist, att_vec, w_zemb,
                                    e_feat, we1, be1, we2, be2);
    // 4 (PROFILED): gate hidden = silu(gin @ wg1 + bg1): 4096 x 128, K=288
    k_bmma<<<dim3(2, NACT_MAX / 128), 256>>>(d_ginH, d_ginL, d_wg1H, d_wg1L, bg1,
                                             d_ghid, nullptr, nullptr, NACT_MAX, 128, KGIN, 1);
    // 5: rad hidden = silu(win @ w1 + b1): 4096 x 128, K=64 -> split
    k_bmma<<<dim3(2, NACT_MAX / 128), 256>>>(d_winH, d_winL, d_w1H, d_w1L, b1_rad,
                                             nullptr, d_hidH, d_hidL, NACT_MAX, 128, KWIN, 2);
    // 6
    k_gate2<<<NACT_MAX / 8, 256>>>(wg2, bg2);
    // 7: tpw = hid @ w2 + b2: 4096 x 4608, K=128
    k_bmma<<<dim3(WN / 64, NACT_MAX / 128), 256>>>(d_hidH, d_hidL, d_w2H, d_w2L, b2_rad,
                                                   d_tpw, nullptr, nullptr, NACT_MAX, WN, HIDN, 0);
    // 8-9
    k_contract<<<NACT_MAX, 128>>>(h_full);
    k_vabs1<<<dim3(BB, 4), 80>>>();
    // 10: invariants + end-of-replay reset
    k_invs<<<(ROWS3 * 24 + 255) / 256, 256>>>();
    // 11-13: tail MLP
    k_bmma<<<dim3(2, ROWS3 / 128), 256>>>(d_invH, d_invL, d_wo1H, d_wo1L, bo1,
                                          nullptr, d_x1H, d_x1L, ROWS3, 128, 48, 2);
    k_bmma<<<dim3(2, ROWS3 / 128), 256>>>(d_x1H, d_x1L, d_wo2H, d_wo2L, bo2,
                                          nullptr, d_x2H, d_x2L, ROWS3, 128, HIDN, 2);
    k_bmma<<<dim3(4, ROWS3 / 128), 256>>>(d_x2H, d_x2L, d_wo3H, d_wo3L, bo3,
                                          out, nullptr, nullptr, ROWS3, 256, HIDN, 0);
}

// round 15
// speedup vs baseline: 1.1187x; 1.0986x over previous
#include <cuda_runtime.h>
#include <cuda_bf16.h>
#include <math.h>
#include <stdint.h>

// ---------------- problem constants ----------------
#define BB        64
#define NN        128
#define FLAT      8192          // B*N
#define H_DIM     128
#define NODE_S    64
#define NODE_V    32
#define OUT_S     32
#define OUT_V     16
#define OUT_DIM   80
#define HIDN      128
#define NEE       512
#define EATT_N    4096
#define WN        4608
#define CUTOFF_F  5.0f
#define NORM_F    0.10206207261596575f   // 1/sqrt(96)
#define SQRT3_F   1.7320508075688772f
#define NACT_MAX  4096
#define ROWS3     32768         // B * NE
#define KWIN      64            // padded 49
#define KGIN      288           // padded 273

// ---------------- scratch (static device memory) ----------------
// g_winner holds edge+1 (0 = inactive). Statically zero-initialized; reset to 0
// at the END of each replay (tail of k_invs) so the graph is idempotent.
__device__ int   g_winner[FLAT];
__device__ int   g_active[FLAT];
__device__ int   g_posmap[FLAT];
__device__ int   g_count;
__device__ float g_ghid  [NACT_MAX * HIDN];
__device__ float g_env   [NACT_MAX];
__device__ float g_mul   [NACT_MAX];
__device__ float g_u     [NACT_MAX * 3];
__device__ float g_tpw   [NACT_MAX * WN];     // 75.5 MB
__device__ float g_vec   [NACT_MAX * OUT_DIM];
__device__ float g_vpart [BB * 4 * OUT_DIM];
__device__ float g_scales[NEE * 48];

// pre-split bf16 hi/lo packed operands (u32 = bf16x2 over consecutive k)
// activations: [row][K/2];  weights: [n][K/2] (transposed at split time)
__device__ __align__(16) unsigned g_winH[NACT_MAX * (KWIN/2)];
__device__ __align__(16) unsigned g_winL[NACT_MAX * (KWIN/2)];
__device__ __align__(16) unsigned g_ginH[NACT_MAX * (KGIN/2)];
__device__ __align__(16) unsigned g_ginL[NACT_MAX * (KGIN/2)];
__device__ __align__(16) unsigned g_hidH[NACT_MAX * (HIDN/2)];
__device__ __align__(16) unsigned g_hidL[NACT_MAX * (HIDN/2)];
__device__ __align__(16) unsigned g_invH[ROWS3 * 24];
__device__ __align__(16) unsigned g_invL[ROWS3 * 24];
__device__ __align__(16) unsigned g_x1H[ROWS3 * 64];
__device__ __align__(16) unsigned g_x1L[ROWS3 * 64];
__device__ __align__(16) unsigned g_x2H[ROWS3 * 64];
__device__ __align__(16) unsigned g_x2L[ROWS3 * 64];
__device__ __align__(16) unsigned g_wg1H[128 * 144];
__device__ __align__(16) unsigned g_wg1L[128 * 144];
__device__ __align__(16) unsigned g_w1H[128 * 32];
__device__ __align__(16) unsigned g_w1L[128 * 32];
__device__ __align__(16) unsigned g_w2H[4608 * 64];
__device__ __align__(16) unsigned g_w2L[4608 * 64];
__device__ __align__(16) unsigned g_wo1H[128 * 24];
__device__ __align__(16) unsigned g_wo1L[128 * 24];
__device__ __align__(16) unsigned g_wo2H[128 * 64];
__device__ __align__(16) unsigned g_wo2L[128 * 64];
__device__ __align__(16) unsigned g_wo3H[256 * 64];
__device__ __align__(16) unsigned g_wo3L[256 * 64];

__device__ __forceinline__ float siluf(float x) { return x / (1.0f + expf(-x)); }
__device__ __forceinline__ float sigmoidf_(float x) { return 1.0f / (1.0f + expf(-x)); }

__device__ __forceinline__ unsigned smem_u32(const void* p) {
    return (unsigned)__cvta_generic_to_shared(p);
}

// split a pair of fp32 into hi/lo bf16x2 packed words (low half = first elem)
__device__ __forceinline__ void split2(float x, float y, unsigned& hi, unsigned& lo) {
    __nv_bfloat162 hh = __floats2bfloat162_rn(x, y);
    float hx = __bfloat162float(__low2bfloat16(hh));
    float hy = __bfloat162float(__high2bfloat16(hh));
    __nv_bfloat162 ll = __floats2bfloat162_rn(x - hx, y - hy);
    hi = *reinterpret_cast<unsigned*>(&hh);
    lo = *reinterpret_cast<unsigned*>(&ll);
}

#define MMA_BF16(c, a, b)                                                        \
    asm volatile(                                                                \
        "mma.sync.aligned.m16n8k16.row.col.f32.bf16.bf16.f32 "                   \
        "{%0,%1,%2,%3},{%4,%5,%6,%7},{%8,%9},{%0,%1,%2,%3};"                     \
        : "+f"((c)[0]), "+f"((c)[1]), "+f"((c)[2]), "+f"((c)[3])                 \
        : "r"((a)[0]), "r"((a)[1]), "r"((a)[2]), "r"((a)[3]),                    \
          "r"((b)[0]), "r"((b)[1]))

#define LDSM4(R0, R1, R2, R3, ADDR)                                              \
    asm volatile(                                                                \
        "ldmatrix.sync.aligned.m8n8.x4.shared.b16 {%0,%1,%2,%3}, [%4];"          \
        : "=r"(R0), "=r"(R1), "=r"(R2), "=r"(R3) : "r"(ADDR))

__device__ __forceinline__ void cpa16(unsigned d, const void* s) {
    asm volatile("cp.async.cg.shared.global [%0], [%1], 16;" :: "r"(d), "l"(s));
}
#define CPA_COMMIT() asm volatile("cp.async.commit_group;" ::: "memory")
#define CPA_WAIT2()  asm volatile("cp.async.wait_group 2;" ::: "memory")

// ---------------- k_initw: edge scatter + weight pre-split (merged) ------------
#define SEG0 18432
#define SEG1 22528
#define SEG2 317440
#define SEG3 320512
#define SEG4 328704
#define SEG5 345088
__global__ void k_initw(const int* __restrict__ att_dst,
                        const float* __restrict__ wg1, const float* __restrict__ w1,
                        const float* __restrict__ w2,  const float* __restrict__ wo1,
                        const float* __restrict__ wo2, const float* __restrict__ wo3)
{
    int i = blockIdx.x * blockDim.x + threadIdx.x;
    if (i < EATT_N) atomicMax(&g_winner[att_dst[i]], i + 1);   // last-write-wins
    if (i >= SEG5) return;
    const float* src; unsigned *H, *L; int Nn, K2, Kreal, li;
    if (i < SEG0)      { src = wg1; H = g_wg1H; L = g_wg1L; Nn = 128;  K2 = 144; Kreal = 273; li = i; }
    else if (i < SEG1) { src = w1;  H = g_w1H;  L = g_w1L;  Nn = 128;  K2 = 32;  Kreal = 49;  li = i - SEG0; }
    else if (i < SEG2) { src = w2;  H = g_w2H;  L = g_w2L;  Nn = 4608; K2 = 64;  Kreal = 128; li = i - SEG1; }
    else if (i < SEG3) { src = wo1; H = g_wo1H; L = g_wo1L; Nn = 128;  K2 = 24;  Kreal = 48;  li = i - SEG2; }
    else if (i < SEG4) { src = wo2; H = g_wo2H; L = g_wo2L; Nn = 128;  K2 = 64;  Kreal = 128; li = i - SEG3; }
    else               { src = wo3; H = g_wo3H; L = g_wo3L; Nn = 256;  K2 = 64;  Kreal = 128; li = i - SEG4; }
    int n = li / K2, kp = li - n * K2;
    int k0 = 2 * kp;
    float x = (k0 < Kreal)     ? src[(size_t)k0 * Nn + n]       : 0.0f;
    float y = (k0 + 1 < Kreal) ? src[(size_t)(k0 + 1) * Nn + n] : 0.0f;
    unsigned hi, lo;
    split2(x, y, hi, lo);
    H[li] = hi; L[li] = lo;
}

__global__ void k_compact() {
    int i = blockIdx.x * blockDim.x + threadIdx.x;
    if (i < FLAT && g_winner[i] > 0) {
        int p = atomicAdd(&g_count, 1);
        g_active[p] = i;
        g_posmap[i] = p;
    }
}

// ---------------- k_prep: split input rows per active node (+scales merged) ----
__global__ void __launch_bounds__(128)
k_prep(const float* __restrict__ h,
       const int*   __restrict__ z,
       const int*   __restrict__ absorber_index,
       const float* __restrict__ att_dist,
       const float* __restrict__ att_vec,
       const float* __restrict__ w_zemb,
       const float* __restrict__ e_feat,
       const float* __restrict__ we1, const float* __restrict__ be1,
       const float* __restrict__ we2, const float* __restrict__ be2)
{
    const int tid = threadIdx.x;
    if (blockIdx.x >= NACT_MAX) {
        __shared__ float hidd[HIDN];
        int e = blockIdx.x - NACT_MAX;
        float acc = be1[tid];
        for (int k = 0; k < 16; k++) acc += e_feat[e * 16 + k] * we1[k * HIDN + tid];
        hidd[tid] = siluf(acc);
        __syncthreads();
        if (tid < 48) {
            float s = be2[tid];
            for (int k = 0; k < HIDN; k++) s += hidd[k] * we2[k * 48 + tid];
            g_scales[e * 48 + tid] = s;
        }
        return;
    }
    const int pos = blockIdx.x;
    if (pos >= g_count) return;
    const int node = g_active[pos];
    const int b = node >> 7, n = node & 127;
    const int e = g_winner[node] - 1;
    const float d = att_dist[e];
    const int absb = absorber_index[b];
    const float isabs = (n == absb) ? 1.0f : 0.0f;
    const float width = CUTOFF_F / 15.0f;
    const float invwidth = 15.0f / CUTOFF_F;
    unsigned hi, lo;

    if (tid < KWIN) {
        float v = 0.0f;
        if (tid < 32)       v = w_zemb[z[node] * 32 + tid];
        else if (tid == 32) v = isabs;
        else if (tid < 49) {
            float t = (d - (float)(tid - 33) * width) * invwidth;
            v = expf(-0.5f * t * t);
        }
        float vp = __shfl_xor_sync(0xffffffffu, v, 1);
        if (!(tid & 1)) {
            split2(v, vp, hi, lo);
            g_winH[pos * 32 + (tid >> 1)] = hi;
            g_winL[pos * 32 + (tid >> 1)] = lo;
        }
    }
    {
        float v = h[(b * NN + absb) * H_DIM + tid];
        float vp = __shfl_xor_sync(0xffffffffu, v, 1);
        if (!(tid & 1)) {
            split2(v, vp, hi, lo);
            g_ginH[pos * 144 + (tid >> 1)] = hi;
            g_ginL[pos * 144 + (tid >> 1)] = lo;
        }
    }
    {
        float v = h[node * H_DIM + tid];
        float vp = __shfl_xor_sync(0xffffffffu, v, 1);
        if (!(tid & 1)) {
            split2(v, vp, hi, lo);
            g_ginH[pos * 144 + 64 + (tid >> 1)] = hi;
            g_ginL[pos * 144 + 64 + (tid >> 1)] = lo;
        }
    }
    if (tid < 32) {
        float v = 0.0f;
        if (tid < 16) {
            float t = (d - (float)tid * width) * invwidth;
            v = expf(-0.5f * t * t);
        } else if (tid == 16) v = isabs;
        float vp = __shfl_xor_sync(0xffffffffu, v, 1);
        if (!(tid & 1)) {
            split2(v, vp, hi, lo);
            g_ginH[pos * 144 + 128 + (tid >> 1)] = hi;
            g_ginL[pos * 144 + 128 + (tid >> 1)] = lo;
        }
    }
    if (tid == 0)
        g_env[pos] = (d < CUTOFF_F) ? 0.5f * (cospif(d / CUTOFF_F) + 1.0f) : 0.0f;
    if (tid < 3)
        g_u[pos * 3 + tid] = att_vec[e * 3 + tid] / fmaxf(d, 1e-8f);
}

// ---------------- k_gate2 ----------------
__global__ void __launch_bounds__(256)
k_gate2(const float* __restrict__ wg2, const float* __restrict__ bg2)
{
    int wid = threadIdx.x >> 5, lane = threadIdx.x & 31;
    int pos = blockIdx.x * 8 + wid;
    if (pos >= g_count) return;
    float s = 0.0f;
#pragma unroll
    for (int j = 0; j < 4; j++) {
        int k = lane + 32 * j;
        s += g_ghid[pos * HIDN + k] * wg2[k];
    }
#pragma unroll
    for (int off = 16; off > 0; off >>= 1) s += __shfl_xor_sync(0xffffffffu, s, off);
    if (lane == 0)
        g_mul[pos] = sigmoidf_(s + bg2[0]) * g_env[pos] * NORM_F;
}

// ================= split-bf16 mma GEMM, 4-stage cp.async pipeline ==============
// C = act(A @ W + bias). Block tile 128x64, BK=16, 256 threads, 8 warps 4x2,
// warp tile 32x32 via m16n8k16. D = AhBh + AhBl + AlBh.
// A: [M][K/2] u32;  W: [n][K/2] u32 (weight pre-transposed at split).
// smem (dynamic): 4 stages x {Ah 6144 | Al 6144 | Wh 3072 | Wl 3072} = 73728 B.
// Rows stride 12 u32 (48B): conflict-free ldmatrix + cp.async stores.
// One commit-group per iteration (possibly empty); wait_group(2) => stage ready.
// mode: 0 = f32 out, 1 = f32 + silu, 2 = split(hi/lo) + silu.
#define STG      4
#define AH_OFF   0
#define AL_OFF   6144
#define WH_OFF   12288
#define WL_OFF   15360
#define STG_B    18432
#define GSMEM    (STG * STG_B)

struct GemmP {
    const unsigned *Ah, *Al, *Wh, *Wl;
    const float* bias;
    float* Cf; unsigned *CH, *CL;
    int N, K, mode;
};

__device__ __forceinline__ void bmma_body(const GemmP p, int bx, int by, char* smem)
{
    const unsigned sbase = smem_u32(smem);
    const int tid = threadIdx.x;
    const int wid = tid >> 5, lane = tid & 31;
    const int wm = wid & 3, wn = wid >> 2;
    const int g = lane >> 2, tig = lane & 3;
    const int m0 = by * 128, n0 = bx * 64;
    const int K2 = p.K >> 1;
    const int nk = p.K >> 4;

    const int ar = tid >> 1, akp = (tid & 1) * 4;
    const int br = tid & 63, bkp = ((tid >> 6) & 1) * 4;

    const int sel = lane >> 3;
    const int lrow = (lane & 7) + (sel & 1) * 8;
    const int lcol = (sel >> 1) * 4;
    const unsigned offA0 = ((wm * 32 + lrow) * 12 + lcol) * 4;
    const unsigned offA1 = ((wm * 32 + 16 + lrow) * 12 + lcol) * 4;
    const unsigned offB0 = ((wn * 32 + lrow) * 12 + lcol) * 4;
    const unsigned offB1 = ((wn * 32 + 16 + lrow) * 12 + lcol) * 4;

    const unsigned adst = sbase + (ar * 12 + akp) * 4;
    const unsigned wdst = sbase + (br * 12 + bkp) * 4;
    const unsigned* agH = p.Ah + (size_t)(m0 + ar) * K2 + akp;
    const unsigned* agL = p.Al + (size_t)(m0 + ar) * K2 + akp;
    const unsigned* wgH = p.Wh + (size_t)(n0 + br) * K2 + bkp;
    const unsigned* wgL = p.Wl + (size_t)(n0 + br) * K2 + bkp;

    float cacc[2][4][4];
#pragma unroll
    for (int mt = 0; mt < 2; mt++)
#pragma unroll
        for (int nt = 0; nt < 4; nt++)
#pragma unroll
            for (int i = 0; i < 4; i++) cacc[mt][nt][i] = 0.0f;

    // prologue: issue stages 0..STG-2
#pragma unroll
    for (int s = 0; s < STG - 1; s++) {
        if (s < nk) {
            unsigned sb = s * STG_B;
            cpa16(adst + sb + AH_OFF, agH + s * 8);
            cpa16(adst + sb + AL_OFF, agL + s * 8);
            if (tid < 128) {
                cpa16(wdst + sb + WH_OFF, wgH + s * 8);
                cpa16(wdst + sb + WL_OFF, wgL + s * 8);
            }
        }
        CPA_COMMIT();
    }

    for (int it = 0; it < nk; it++) {
        CPA_WAIT2();
        __syncthreads();
        const int buf = it & (STG - 1);
        const unsigned bb = sbase + buf * STG_B;
        const unsigned bAh = bb + AH_OFF, bAl = bb + AL_OFF;
        const unsigned bWh = bb + WH_OFF, bWl = bb + WL_OFF;

        unsigned Ah[2][4], Al[2][4], Bh[4][2], Bl[4][2];
        LDSM4(Ah[0][0], Ah[0][1], Ah[0][2], Ah[0][3], bAh + offA0);
        LDSM4(Ah[1][0], Ah[1][1], Ah[1][2], Ah[1][3], bAh + offA1);
        LDSM4(Al[0][0], Al[0][1], Al[0][2], Al[0][3], bAl + offA0);
        LDSM4(Al[1][0], Al[1][1], Al[1][2], Al[1][3], bAl + offA1);
        LDSM4(Bh[0][0], Bh[1][0], Bh[0][1], Bh[1][1], bWh + offB0);
        LDSM4(Bh[2][0], Bh[3][0], Bh[2][1], Bh[3][1], bWh + offB1);
        LDSM4(Bl[0][0], Bl[1][0], Bl[0][1], Bl[1][1], bWl + offB0);
        LDSM4(Bl[2][0], Bl[3][0], Bl[2][1], Bl[3][1], bWl + offB1);

        // issue stage it+STG-1 (writes buf (it-1)%STG, released at this sync)
        int s = it + STG - 1;
        if (s < nk) {
            unsigned sb = (s & (STG - 1)) * STG_B;
            cpa16(adst + sb + AH_OFF, agH + s * 8);
            cpa16(adst + sb + AL_OFF, agL + s * 8);
            if (tid < 128) {
                cpa16(wdst + sb + WH_OFF, wgH + s * 8);
                cpa16(wdst + sb + WL_OFF, wgL + s * 8);
            }
        }
        CPA_COMMIT();

#pragma unroll
        for (int mt = 0; mt < 2; mt++)
#pragma unroll
            for (int nt = 0; nt < 4; nt++) {
                MMA_BF16(cacc[mt][nt], Ah[mt], Bh[nt]);
                MMA_BF16(cacc[mt][nt], Ah[mt], Bl[nt]);
                MMA_BF16(cacc[mt][nt], Al[mt], Bh[nt]);
            }
    }

    // ---- epilogue ----
    const int N2 = p.N >> 1;
#pragma unroll
    for (int mt = 0; mt < 2; mt++) {
        int row0 = m0 + wm * 32 + mt * 16 + g;
#pragma unroll
        for (int nt = 0; nt < 4; nt++) {
            int col = n0 + wn * 32 + nt * 8 + 2 * tig;
            float b0 = p.bias[col], b1 = p.bias[col + 1];
            float v00 = cacc[mt][nt][0] + b0;
            float v01 = cacc[mt][nt][1] + b1;
            float v10 = cacc[mt][nt][2] + b0;
            float v11 = cacc[mt][nt][3] + b1;
            if (p.mode != 0) { v00 = siluf(v00); v01 = siluf(v01); v10 = siluf(v10); v11 = siluf(v11); }
            if (p.mode == 2) {
                unsigned hi, lo;
                split2(v00, v01, hi, lo);
                p.CH[(size_t)row0 * N2 + (col >> 1)] = hi;
                p.CL[(size_t)row0 * N2 + (col >> 1)] = lo;
                split2(v10, v11, hi, lo);
                p.CH[(size_t)(row0 + 8) * N2 + (col >> 1)] = hi;
                p.CL[(size_t)(row0 + 8) * N2 + (col >> 1)] = lo;
            } else {
                float2 r0 = {v00, v01};
                float2 r1 = {v10, v11};
                *reinterpret_cast<float2*>(p.Cf + (size_t)row0 * p.N + col) = r0;
                *reinterpret_cast<float2*>(p.Cf + (size_t)(row0 + 8) * p.N + col) = r1;
            }
        }
    }
}

__global__ void __launch_bounds__(256, 2)
k_bmma(GemmP p)
{
    extern __shared__ char smem[];
    bmma_body(p, blockIdx.x, blockIdx.y, smem);
}

// dual GEMM: blocks with x < split run p0 (cols bx), others p1 (cols bx-split)
__global__ void __launch_bounds__(256, 2)
k_bmma2(GemmP p0, GemmP p1, int split)
{
    extern __shared__ char smem[];
    if ((int)blockIdx.x < split) bmma_body(p0, blockIdx.x, blockIdx.y, smem);
    else                         bmma_body(p1, blockIdx.x - split, blockIdx.y, smem);
}

// ---------------- k_contract: tpw(4608) x node tensors -> vec[pos][80] ---------
__global__ void __launch_bounds__(128)
k_contract(const float* __restrict__ h_full)
{
    __shared__ float s1[NODE_S];
    __shared__ float v1s[NODE_V * 3];
    __shared__ float bvi[NODE_V];
    __shared__ float uu[3];

    const int pos = blockIdx.x;
    if (pos >= g_count) return;
    const int tid = threadIdx.x;
    const int node = g_active[pos];
    const float* hf = h_full + (size_t)node * 160;

    if (tid < NODE_S) s1[tid] = hf[tid];
    if (tid < NODE_V * 3) v1s[tid] = hf[NODE_S + tid];
    if (tid < 3) uu[tid] = g_u[pos * 3 + tid];
    __syncthreads();
    if (tid < NODE_V)
        bvi[tid] = v1s[3 * tid] * uu[0] + v1s[3 * tid + 1] * uu[1] + v1s[3 * tid + 2] * uu[2];
    __syncthreads();

    const float* tp = g_tpw + (size_t)pos * WN;
    const float mul = g_mul[pos];

    if (tid < OUT_S) {
        int o = tid;
        float acc = 0.0f;
#pragma unroll 8
        for (int i = 0; i < NODE_S; i++) acc += s1[i] * tp[i * OUT_S + o];
#pragma unroll 8
        for (int i = 0; i < NODE_V; i++) acc += bvi[i] * tp[2048 + i * OUT_S + o];
        g_vec[(size_t)pos * OUT_DIM + o] = acc * mul;
    }
    if (tid >= 64 && tid < 112) {
        int t = tid - 64;
        int o = t & 15, c = t >> 4;      // o<16, c<3
        float sc = 0.0f, sd = 0.0f;
#pragma unroll 8
        for (int i = 0; i < NODE_S; i++) sc += s1[i] * tp[3072 + i * OUT_V + o];
#pragma unroll 8
        for (int i = 0; i < NODE_V; i++) sd += v1s[3 * i + c] * tp[4096 + i * OUT_V + o];
        float yv = SQRT3_F * uu[c];
        g_vec[(size_t)pos * OUT_DIM + OUT_S + o * 3 + c] = (sc * yv + sd) * mul;
    }
}

// ---------------- k_vabs1: deterministic per-batch partial reduce ---------------
__global__ void k_vabs1() {
    int b = blockIdx.x, ch = blockIdx.y, t = threadIdx.x;
    if (t >= OUT_DIM) return;
    float acc = 0.0f;
    int nbase = b * NN + ch * 32;
    for (int n = 0; n < 32; n++) {
        int node = nbase + n;
        if (g_winner[node] > 0)
            acc += g_vec[(size_t)g_posmap[node] * OUT_DIM + t];
    }
    g_vpart[(b * 4 + ch) * OUT_DIM + t] = acc;
}

// ---------------- k_invs: invariants (split bf16) + end-of-replay reset --------
__device__ __forceinline__ float vabs_of(int b, int j) {
    float a = g_vpart[(b * 4 + 0) * OUT_DIM + j];
    a += g_vpart[(b * 4 + 1) * OUT_DIM + j];
    a += g_vpart[(b * 4 + 2) * OUT_DIM + j];
    a += g_vpart[(b * 4 + 3) * OUT_DIM + j];
    return a;
}

__global__ void __launch_bounds__(256)
k_invs()
{
    int t = blockIdx.x * blockDim.x + threadIdx.x;
    if (t < FLAT) g_winner[t] = 0;
    if (t == 0)   g_count = 0;
    if (t >= ROWS3 * 24) return;
    int row = t / 24, jp = t - row * 24;
    int b = row >> 9, e = row & 511;
    float vals[2];
#pragma unroll
    for (int jj = 0; jj < 2; jj++) {
        int j = 2 * jp + jj;
        float v;
        if (j < OUT_S) {
            v = vabs_of(b, j) * g_scales[e * 48 + j];
        } else {
            int o = j - OUT_S;
            float s = g_scales[e * 48 + OUT_S + o];
            float x0 = vabs_of(b, OUT_S + o * 3 + 0) * s;
            float x1 = vabs_of(b, OUT_S + o * 3 + 1) * s;
            float x2 = vabs_of(b, OUT_S + o * 3 + 2) * s;
            v = sqrtf(x0 * x0 + x1 * x1 + x2 * x2 + 1e-12f);
        }
        vals[jj] = v;
    }
    unsigned hi, lo;
    split2(vals[0], vals[1], hi, lo);
    g_invH[row * 24 + jp] = hi;
    g_invL[row * 24 + jp] = lo;
}

// ---------------- launch ----------------
extern "C" void kernel_launch(void* const* d_in, const int* in_sizes, int n_in,
                              void* d_out, int out_size)
{
    const float* h        = (const float*)d_in[0];
    const float* h_full   = (const float*)d_in[1];
    const int*   z        = (const int*)  d_in[2];
    const float* e_feat   = (const float*)d_in[4];
    const int*   abs_idx  = (const int*)  d_in[5];
    const int*   att_dst  = (const int*)  d_in[6];
    const float* att_dist = (const float*)d_in[7];
    const float* att_vec  = (const float*)d_in[8];
    const float* w_zemb   = (const float*)d_in[9];
    const float* w1_rad   = (const float*)d_in[10];
    const float* b1_rad   = (const float*)d_in[11];
    const float* w2_rad   = (const float*)d_in[12];
    const float* b2_rad   = (const float*)d_in[13];
    const float* wg1      = (const float*)d_in[14];
    const float* bg1      = (const float*)d_in[15];
    const float* wg2      = (const float*)d_in[16];
    const float* bg2      = (const float*)d_in[17];
    const float* we1      = (const float*)d_in[18];
    const float* be1      = (const float*)d_in[19];
    const float* we2      = (const float*)d_in[20];
    const float* be2      = (const float*)d_in[21];
    const float* wo1      = (const float*)d_in[22];
    const float* bo1      = (const float*)d_in[23];
    const float* wo2      = (const float*)d_in[24];
    const float* bo2      = (const float*)d_in[25];
    const float* wo3      = (const float*)d_in[26];
    const float* bo3      = (const float*)d_in[27];
    float* out = (float*)d_out;

    float *d_ghid, *d_tpw;
    unsigned *d_winH, *d_winL, *d_ginH, *d_ginL, *d_hidH, *d_hidL;
    unsigned *d_invH, *d_invL, *d_x1H, *d_x1L, *d_x2H, *d_x2L;
    unsigned *d_wg1H, *d_wg1L, *d_w1H, *d_w1L, *d_w2H, *d_w2L;
    unsigned *d_wo1H, *d_wo1L, *d_wo2H, *d_wo2L, *d_wo3H, *d_wo3L;
    cudaGetSymbolAddress((void**)&d_ghid, g_ghid);
    cudaGetSymbolAddress((void**)&d_tpw,  g_tpw);
    cudaGetSymbolAddress((void**)&d_winH, g_winH);
    cudaGetSymbolAddress((void**)&d_winL, g_winL);
    cudaGetSymbolAddress((void**)&d_ginH, g_ginH);
    cudaGetSymbolAddress((void**)&d_ginL, g_ginL);
    cudaGetSymbolAddress((void**)&d_hidH, g_hidH);
    cudaGetSymbolAddress((void**)&d_hidL, g_hidL);
    cudaGetSymbolAddress((void**)&d_invH, g_invH);
    cudaGetSymbolAddress((void**)&d_invL, g_invL);
    cudaGetSymbolAddress((void**)&d_x1H,  g_x1H);
    cudaGetSymbolAddress((void**)&d_x1L,  g_x1L);
    cudaGetSymbolAddress((void**)&d_x2H,  g_x2H);
    cudaGetSymbolAddress((void**)&d_x2L,  g_x2L);
    cudaGetSymbolAddress((void**)&d_wg1H, g_wg1H);
    cudaGetSymbolAddress((void**)&d_wg1L, g_wg1L);
    cudaGetSymbolAddress((void**)&d_w1H,  g_w1H);
    cudaGetSymbolAddress((void**)&d_w1L,  g_w1L);
    cudaGetSymbolAddress((void**)&d_w2H,  g_w2H);
    cudaGetSymbolAddress((void**)&d_w2L,  g_w2L);
    cudaGetSymbolAddress((void**)&d_wo1H, g_wo1H);
    cudaGetSymbolAddress((void**)&d_wo1L, g_wo1L);
    cudaGetSymbolAddress((void**)&d_wo2H, g_wo2H);
    cudaGetSymbolAddress((void**)&d_wo2L, g_wo2L);
    cudaGetSymbolAddress((void**)&d_wo3H, g_wo3H);
    cudaGetSymbolAddress((void**)&d_wo3L, g_wo3L);

    cudaFuncSetAttribute(k_bmma,  cudaFuncAttributeMaxDynamicSharedMemorySize, GSMEM);
    cudaFuncSetAttribute(k_bmma2, cudaFuncAttributeMaxDynamicSharedMemorySize, GSMEM);

    // 1: edge scatter + weight split
    k_initw<<<(SEG5 + 255) / 256, 256>>>(att_dst, wg1, w1_rad, w2_rad, wo1, wo2, wo3);
    // 2: compact active nodes
    k_compact<<<(FLAT + 255) / 256, 256>>>();
    // 3: per-node input prep + scales MLP
    k_prep<<<NACT_MAX + NEE, 128>>>(h, z, abs_idx, att_dist, att_vec, w_zemb,
                                    e_feat, we1, be1, we2, be2);

    GemmP pg = {d_ginH, d_ginL, d_wg1H, d_wg1L, bg1, d_ghid, nullptr, nullptr, 128, KGIN, 1};
    GemmP pr = {d_winH, d_winL, d_w1H, d_w1L, b1_rad, nullptr, d_hidH, d_hidL, 128, KWIN, 2};
    // 4 (PROFILED): fused gate (4096x128,K=288) + rad (4096x128,K=64)
    k_bmma2<<<dim3(4, NACT_MAX / 128), 256, GSMEM>>>(pg, pr, 2);
    // 5
    k_gate2<<<NACT_MAX / 8, 256>>>(wg2, bg2);
    // 6: tpw = hid @ w2 + b2: 4096 x 4608, K=128
    GemmP pt = {d_hidH, d_hidL, d_w2H, d_w2L, b2_rad, d_tpw, nullptr, nullptr, WN, HIDN, 0};
    k_bmma<<<dim3(WN / 64, NACT_MAX / 128), 256, GSMEM>>>(pt);
    // 7-8
    k_contract<<<NACT_MAX, 128>>>(h_full);
    k_vabs1<<<dim3(BB, 4), 80>>>();
    // 9: invariants + end-of-replay reset
    k_invs<<<(ROWS3 * 24 + 255) / 256, 256>>>();
    // 10-12: tail MLP
    GemmP p1 = {d_invH, d_invL, d_wo1H, d_wo1L, bo1, nullptr, d_x1H, d_x1L, 128, 48, 2};
    k_bmma<<<dim3(2, ROWS3 / 128), 256, GSMEM>>>(p1);
    GemmP p2 = {d_x1H, d_x1L, d_wo2H, d_wo2L, bo2, nullptr, d_x2H, d_x2L, 128, HIDN, 2};
    k_bmma<<<dim3(2, ROWS3 / 128), 256, GSMEM>>>(p2);
    GemmP p3 = {d_x2H, d_x2L, d_wo3H, d_wo3L, bo3, out, nullptr, nullptr, 256, HIDN, 0};
    k_bmma<<<dim3(4, ROWS3 / 128), 256, GSMEM>>>(p3);
}

// round 16
// speedup vs baseline: 1.1500x; 1.0280x over previous
#include <cuda_runtime.h>
#include <cuda_bf16.h>
#include <math.h>
#include <stdint.h>

// ---------------- problem constants ----------------
#define BB        64
#define NN        128
#define FLAT      8192          // B*N
#define H_DIM     128
#define NODE_S    64
#define NODE_V    32
#define OUT_S     32
#define OUT_V     16
#define OUT_DIM   80
#define HIDN      128
#define NEE       512
#define EATT_N    4096
#define WN        4608
#define CUTOFF_F  5.0f
#define NORM_F    0.10206207261596575f   // 1/sqrt(96)
#define SQRT3_F   1.7320508075688772f
#define NACT_MAX  4096
#define ROWS3     32768         // B * NE
#define KWIN      64            // padded 49
#define KGIN      288           // padded 273

// ---------------- scratch (static device memory) ----------------
// g_winner holds edge+1 (0 = inactive). Statically zero-initialized; reset to 0
// at the END of each replay (tail of k_invs) so the graph is idempotent.
__device__ int   g_winner[FLAT];
__device__ int   g_active[FLAT];
__device__ int   g_posmap[FLAT];
__device__ int   g_count;
__device__ float g_ghid  [NACT_MAX * HIDN];
__device__ float g_env   [NACT_MAX];
__device__ float g_mul   [NACT_MAX];
__device__ float g_u     [NACT_MAX * 3];
__device__ float g_tpw   [NACT_MAX * WN];     // 75.5 MB
__device__ float g_vec   [NACT_MAX * OUT_DIM];
__device__ float g_vpart [BB * 4 * OUT_DIM];
__device__ float g_scales[NEE * 48];

// pre-split bf16 hi/lo packed operands (u32 = bf16x2 over consecutive k)
// activations: [row][K/2];  weights: [n][K/2] (transposed at split time)
__device__ __align__(16) unsigned g_winH[NACT_MAX * (KWIN/2)];
__device__ __align__(16) unsigned g_winL[NACT_MAX * (KWIN/2)];
__device__ __align__(16) unsigned g_ginH[NACT_MAX * (KGIN/2)];
__device__ __align__(16) unsigned g_ginL[NACT_MAX * (KGIN/2)];
__device__ __align__(16) unsigned g_hidH[NACT_MAX * (HIDN/2)];
__device__ __align__(16) unsigned g_hidL[NACT_MAX * (HIDN/2)];
__device__ __align__(16) unsigned g_invH[ROWS3 * 24];
__device__ __align__(16) unsigned g_invL[ROWS3 * 24];
__device__ __align__(16) unsigned g_x1H[ROWS3 * 64];
__device__ __align__(16) unsigned g_x1L[ROWS3 * 64];
__device__ __align__(16) unsigned g_x2H[ROWS3 * 64];
__device__ __align__(16) unsigned g_x2L[ROWS3 * 64];
__device__ __align__(16) unsigned g_wg1H[128 * 144];
__device__ __align__(16) unsigned g_wg1L[128 * 144];
__device__ __align__(16) unsigned g_w1H[128 * 32];
__device__ __align__(16) unsigned g_w1L[128 * 32];
__device__ __align__(16) unsigned g_w2H[4608 * 64];
__device__ __align__(16) unsigned g_w2L[4608 * 64];
__device__ __align__(16) unsigned g_wo1H[128 * 24];
__device__ __align__(16) unsigned g_wo1L[128 * 24];
__device__ __align__(16) unsigned g_wo2H[128 * 64];
__device__ __align__(16) unsigned g_wo2L[128 * 64];
__device__ __align__(16) unsigned g_wo3H[256 * 64];
__device__ __align__(16) unsigned g_wo3L[256 * 64];

__device__ __forceinline__ float siluf(float x) { return x / (1.0f + expf(-x)); }
__device__ __forceinline__ float sigmoidf_(float x) { return 1.0f / (1.0f + expf(-x)); }

__device__ __forceinline__ unsigned smem_u32(const void* p) {
    return (unsigned)__cvta_generic_to_shared(p);
}

// split a pair of fp32 into hi/lo bf16x2 packed words (low half = first elem)
__device__ __forceinline__ void split2(float x, float y, unsigned& hi, unsigned& lo) {
    __nv_bfloat162 hh = __floats2bfloat162_rn(x, y);
    float hx = __bfloat162float(__low2bfloat16(hh));
    float hy = __bfloat162float(__high2bfloat16(hh));
    __nv_bfloat162 ll = __floats2bfloat162_rn(x - hx, y - hy);
    hi = *reinterpret_cast<unsigned*>(&hh);
    lo = *reinterpret_cast<unsigned*>(&ll);
}

#define MMA_BF16(c, a, b)                                                        \
    asm volatile(                                                                \
        "mma.sync.aligned.m16n8k16.row.col.f32.bf16.bf16.f32 "                   \
        "{%0,%1,%2,%3},{%4,%5,%6,%7},{%8,%9},{%0,%1,%2,%3};"                     \
        : "+f"((c)[0]), "+f"((c)[1]), "+f"((c)[2]), "+f"((c)[3])                 \
        : "r"((a)[0]), "r"((a)[1]), "r"((a)[2]), "r"((a)[3]),                    \
          "r"((b)[0]), "r"((b)[1]))

#define LDSM4(R0, R1, R2, R3, ADDR)                                              \
    asm volatile(                                                                \
        "ldmatrix.sync.aligned.m8n8.x4.shared.b16 {%0,%1,%2,%3}, [%4];"          \
        : "=r"(R0), "=r"(R1), "=r"(R2), "=r"(R3) : "r"(ADDR))

__device__ __forceinline__ void cpa16(unsigned d, const void* s) {
    asm volatile("cp.async.cg.shared.global [%0], [%1], 16;" :: "r"(d), "l"(s));
}
#define CPA_COMMIT() asm volatile("cp.async.commit_group;" ::: "memory")
#define CPA_WAIT2()  asm volatile("cp.async.wait_group 2;" ::: "memory")

// ---------------- k_initw: edge scatter + weight pre-split (merged) ------------
#define SEG0 18432
#define SEG1 22528
#define SEG2 317440
#define SEG3 320512
#define SEG4 328704
#define SEG5 345088
__global__ void k_initw(const int* __restrict__ att_dst,
                        const float* __restrict__ wg1, const float* __restrict__ w1,
                        const float* __restrict__ w2,  const float* __restrict__ wo1,
                        const float* __restrict__ wo2, const float* __restrict__ wo3)
{
    int i = blockIdx.x * blockDim.x + threadIdx.x;
    if (i < EATT_N) atomicMax(&g_winner[att_dst[i]], i + 1);   // last-write-wins
    if (i >= SEG5) return;
    const float* src; unsigned *H, *L; int Nn, K2, Kreal, li;
    if (i < SEG0)      { src = wg1; H = g_wg1H; L = g_wg1L; Nn = 128;  K2 = 144; Kreal = 273; li = i; }
    else if (i < SEG1) { src = w1;  H = g_w1H;  L = g_w1L;  Nn = 128;  K2 = 32;  Kreal = 49;  li = i - SEG0; }
    else if (i < SEG2) { src = w2;  H = g_w2H;  L = g_w2L;  Nn = 4608; K2 = 64;  Kreal = 128; li = i - SEG1; }
    else if (i < SEG3) { src = wo1; H = g_wo1H; L = g_wo1L; Nn = 128;  K2 = 24;  Kreal = 48;  li = i - SEG2; }
    else if (i < SEG4) { src = wo2; H = g_wo2H; L = g_wo2L; Nn = 128;  K2 = 64;  Kreal = 128; li = i - SEG3; }
    else               { src = wo3; H = g_wo3H; L = g_wo3L; Nn = 256;  K2 = 64;  Kreal = 128; li = i - SEG4; }
    int n = li / K2, kp = li - n * K2;
    int k0 = 2 * kp;
    float x = (k0 < Kreal)     ? src[(size_t)k0 * Nn + n]       : 0.0f;
    float y = (k0 + 1 < Kreal) ? src[(size_t)(k0 + 1) * Nn + n] : 0.0f;
    unsigned hi, lo;
    split2(x, y, hi, lo);
    H[li] = hi; L[li] = lo;
}

__global__ void k_compact() {
    int i = blockIdx.x * blockDim.x + threadIdx.x;
    if (i < FLAT && g_winner[i] > 0) {
        int p = atomicAdd(&g_count, 1);
        g_active[p] = i;
        g_posmap[i] = p;
    }
}

// ---------------- k_prep: warp-per-pos input prep (+scales blocks) -------------
#define PREP_POS_BLOCKS (NACT_MAX / 4)
__global__ void __launch_bounds__(128)
k_prep(const float* __restrict__ h,
       const int*   __restrict__ z,
       const int*   __restrict__ absorber_index,
       const float* __restrict__ att_dist,
       const float* __restrict__ att_vec,
       const float* __restrict__ w_zemb,
       const float* __restrict__ e_feat,
       const float* __restrict__ we1, const float* __restrict__ be1,
       const float* __restrict__ we2, const float* __restrict__ be2)
{
    const int tid = threadIdx.x;
    if (blockIdx.x >= PREP_POS_BLOCKS) {
        // ---- scales MLP: one block per edge type ----
        __shared__ float hidd[HIDN];
        int e = blockIdx.x - PREP_POS_BLOCKS;
        float acc = be1[tid];
        for (int k = 0; k < 16; k++) acc += e_feat[e * 16 + k] * we1[k * HIDN + tid];
        hidd[tid] = siluf(acc);
        __syncthreads();
        if (tid < 48) {
            float s = be2[tid];
            for (int k = 0; k < HIDN; k++) s += hidd[k] * we2[k * 48 + tid];
            g_scales[e * 48 + tid] = s;
        }
        return;
    }
    const int warp = tid >> 5, lane = tid & 31;
    const int pos = blockIdx.x * 4 + warp;
    if (pos >= g_count) return;
    const int node = g_active[pos];
    const int b = node >> 7, n = node & 127;
    const int e = g_winner[node] - 1;
    const float d = att_dist[e];
    const int absb = absorber_index[b];
    const float isabs = (n == absb) ? 1.0f : 0.0f;
    const float width = CUTOFF_F / 15.0f;
    const float invwidth = 15.0f / CUTOFF_F;
    const int zn = z[node];
    unsigned hi, lo;

    // win row (64 padded, 49 used): [zemb 32 | isabs | rbf 16 | pad]
#pragma unroll
    for (int half = 0; half < 2; half++) {
        int j = half * 32 + lane;
        float v = 0.0f;
        if (j < 32)       v = w_zemb[zn * 32 + j];
        else if (j == 32) v = isabs;
        else if (j < 49) {
            float t = (d - (float)(j - 33) * width) * invwidth;
            v = expf(-0.5f * t * t);
        }
        float vp = __shfl_xor_sync(0xffffffffu, v, 1);
        if (!(lane & 1)) {
            split2(v, vp, hi, lo);
            g_winH[pos * 32 + (j >> 1)] = hi;
            g_winL[pos * 32 + (j >> 1)] = lo;
        }
    }
    // gin row: [h_abs 128 | h 128 | rbf16+isabs+pad 32]
    const float* habs = h + (size_t)(b * NN + absb) * H_DIM;
    const float* hown = h + (size_t)node * H_DIM;
#pragma unroll
    for (int c4 = 0; c4 < 4; c4++) {
        int j = c4 * 32 + lane;
        float v = habs[j];
        float vp = __shfl_xor_sync(0xffffffffu, v, 1);
        if (!(lane & 1)) {
            split2(v, vp, hi, lo);
            g_ginH[pos * 144 + (j >> 1)] = hi;
            g_ginL[pos * 144 + (j >> 1)] = lo;
        }
    }
#pragma unroll
    for (int c4 = 0; c4 < 4; c4++) {
        int j = c4 * 32 + lane;
        float v = hown[j];
        float vp = __shfl_xor_sync(0xffffffffu, v, 1);
        if (!(lane & 1)) {
            split2(v, vp, hi, lo);
            g_ginH[pos * 144 + 64 + (j >> 1)] = hi;
            g_ginL[pos * 144 + 64 + (j >> 1)] = lo;
        }
    }
    {
        float v = 0.0f;
        if (lane < 16) {
            float t = (d - (float)lane * width) * invwidth;
            v = expf(-0.5f * t * t);
        } else if (lane == 16) v = isabs;
        float vp = __shfl_xor_sync(0xffffffffu, v, 1);
        if (!(lane & 1)) {
            split2(v, vp, hi, lo);
            g_ginH[pos * 144 + 128 + (lane >> 1)] = hi;
            g_ginL[pos * 144 + 128 + (lane >> 1)] = lo;
        }
    }
    if (lane == 0)
        g_env[pos] = (d < CUTOFF_F) ? 0.5f * (cospif(d / CUTOFF_F) + 1.0f) : 0.0f;
    if (lane < 3)
        g_u[pos * 3 + lane] = att_vec[e * 3 + lane] / fmaxf(d, 1e-8f);
}

// ---------------- k_gate2 ----------------
__global__ void __launch_bounds__(256)
k_gate2(const float* __restrict__ wg2, const float* __restrict__ bg2)
{
    int wid = threadIdx.x >> 5, lane = threadIdx.x & 31;
    int pos = blockIdx.x * 8 + wid;
    if (pos >= g_count) return;
    float s = 0.0f;
#pragma unroll
    for (int j = 0; j < 4; j++) {
        int k = lane + 32 * j;
        s += g_ghid[pos * HIDN + k] * wg2[k];
    }
#pragma unroll
    for (int off = 16; off > 0; off >>= 1) s += __shfl_xor_sync(0xffffffffu, s, off);
    if (lane == 0)
        g_mul[pos] = sigmoidf_(s + bg2[0]) * g_env[pos] * NORM_F;
}

// ================= split-bf16 mma GEMM, 4-stage cp.async pipeline ==============
// C = act(A @ W + bias). Block tile (64*MT)x64, BK=16, 256 threads, 8 warps 4x2,
// warp tile (16*MT)x32 via m16n8k16. D = AhBh + AhBl + AlBh.
// A: [M][K/2] u32;  W: [n][K/2] u32 (weight pre-transposed at split).
// Rows stride 12 u32 (48B): conflict-free ldmatrix + cp.async stores.
// One commit-group per iteration (possibly empty); wait_group(2) => stage ready.
// mode: 0 = f32 out, 1 = f32 + silu, 2 = split(hi/lo) + silu.
#define STG 4

struct GemmP {
    const unsigned *Ah, *Al, *Wh, *Wl;
    const float* bias;
    float* Cf; unsigned *CH, *CL;
    int N, K, mode;
};

template<int MT>
__device__ __forceinline__ void bmma_body(const GemmP p, int bx, int by, char* smem)
{
    constexpr int AROWS = 64 * MT;
    constexpr int AHSZ  = AROWS * 12 * 4;   // bytes per A tile (hi or lo)
    constexpr int WHSZ  = 64 * 12 * 4;      // 3072
    constexpr int AH_O  = 0;
    constexpr int AL_O  = AHSZ;
    constexpr int WH_O  = 2 * AHSZ;
    constexpr int WL_O  = 2 * AHSZ + WHSZ;
    constexpr int STGB  = 2 * AHSZ + 2 * WHSZ;

    const unsigned sbase = smem_u32(smem);
    const int tid = threadIdx.x;
    const int wid = tid >> 5, lane = tid & 31;
    const int wm = wid & 3, wn = wid >> 2;
    const int g = lane >> 2, tig = lane & 3;
    const int m0 = by * AROWS, n0 = bx * 64;
    const int K2 = p.K >> 1;
    const int nk = p.K >> 4;

    int ar, akp, br, bkp;
    bool doA, doW;
    if (MT == 2) {
        ar = tid >> 1; akp = (tid & 1) * 4; doA = true;
        br = tid & 63; bkp = ((tid >> 6) & 1) * 4; doW = (tid < 128);
    } else {
        doA = (tid < 128);
        ar = (tid & 127) >> 1; akp = (tid & 1) * 4;
        doW = (tid >= 128);
        br = (tid & 127) >> 1; bkp = (tid & 1) * 4;
    }

    const int sel = lane >> 3;
    const int lrow = (lane & 7) + (sel & 1) * 8;
    const int lcol = (sel >> 1) * 4;
    const int wrb = wm * 16 * MT;
    unsigned offA[MT];
#pragma unroll
    for (int mt = 0; mt < MT; mt++)
        offA[mt] = ((wrb + mt * 16 + lrow) * 12 + lcol) * 4;
    const unsigned offB0 = ((wn * 32 + lrow) * 12 + lcol) * 4;
    const unsigned offB1 = ((wn * 32 + 16 + lrow) * 12 + lcol) * 4;

    const unsigned adst = sbase + (ar * 12 + akp) * 4;
    const unsigned wdst = sbase + (br * 12 + bkp) * 4;
    const unsigned* agH = p.Ah + (size_t)(m0 + ar) * K2 + akp;
    const unsigned* agL = p.Al + (size_t)(m0 + ar) * K2 + akp;
    const unsigned* wgH = p.Wh + (size_t)(n0 + br) * K2 + bkp;
    const unsigned* wgL = p.Wl + (size_t)(n0 + br) * K2 + bkp;

    float cacc[MT][4][4];
#pragma unroll
    for (int mt = 0; mt < MT; mt++)
#pragma unroll
        for (int nt = 0; nt < 4; nt++)
#pragma unroll
            for (int i = 0; i < 4; i++) cacc[mt][nt][i] = 0.0f;

    // prologue: issue stages 0..STG-2
#pragma unroll
    for (int s = 0; s < STG - 1; s++) {
        if (s < nk) {
            unsigned sb = s * STGB;
            if (doA) {
                cpa16(adst + sb + AH_O, agH + s * 8);
                cpa16(adst + sb + AL_O, agL + s * 8);
            }
            if (doW) {
                cpa16(wdst + sb + WH_O, wgH + s * 8);
                cpa16(wdst + sb + WL_O, wgL + s * 8);
            }
        }
        CPA_COMMIT();
    }

    for (int it = 0; it < nk; it++) {
        CPA_WAIT2();
        __syncthreads();
        const int buf = it & (STG - 1);
        const unsigned bb = sbase + buf * STGB;
        const unsigned bAh = bb + AH_O, bAl = bb + AL_O;
        const unsigned bWh = bb + WH_O, bWl = bb + WL_O;

        unsigned Ah[MT][4], Al[MT][4], Bh[4][2], Bl[4][2];
#pragma unroll
        for (int mt = 0; mt < MT; mt++) {
            LDSM4(Ah[mt][0], Ah[mt][1], Ah[mt][2], Ah[mt][3], bAh + offA[mt]);
            LDSM4(Al[mt][0], Al[mt][1], Al[mt][2], Al[mt][3], bAl + offA[mt]);
        }
        LDSM4(Bh[0][0], Bh[1][0], Bh[0][1], Bh[1][1], bWh + offB0);
        LDSM4(Bh[2][0], Bh[3][0], Bh[2][1], Bh[3][1], bWh + offB1);
        LDSM4(Bl[0][0], Bl[1][0], Bl[0][1], Bl[1][1], bWl + offB0);
        LDSM4(Bl[2][0], Bl[3][0], Bl[2][1], Bl[3][1], bWl + offB1);

        int s = it + STG - 1;
        if (s < nk) {
            unsigned sb = (s & (STG - 1)) * STGB;
            if (doA) {
                cpa16(adst + sb + AH_O, agH + s * 8);
                cpa16(adst + sb + AL_O, agL + s * 8);
            }
            if (doW) {
                cpa16(wdst + sb + WH_O, wgH + s * 8);
                cpa16(wdst + sb + WL_O, wgL + s * 8);
            }
        }
        CPA_COMMIT();

#pragma unroll
        for (int mt = 0; mt < MT; mt++)
#pragma unroll
            for (int nt = 0; nt < 4; nt++) {
                MMA_BF16(cacc[mt][nt], Ah[mt], Bh[nt]);
                MMA_BF16(cacc[mt][nt], Ah[mt], Bl[nt]);
                MMA_BF16(cacc[mt][nt], Al[mt], Bh[nt]);
            }
    }

    // ---- epilogue ----
    const int N2 = p.N >> 1;
#pragma unroll
    for (int mt = 0; mt < MT; mt++) {
        int row0 = m0 + wrb + mt * 16 + g;
#pragma unroll
        for (int nt = 0; nt < 4; nt++) {
            int col = n0 + wn * 32 + nt * 8 + 2 * tig;
            float b0 = p.bias[col], b1 = p.bias[col + 1];
            float v00 = cacc[mt][nt][0] + b0;
            float v01 = cacc[mt][nt][1] + b1;
            float v10 = cacc[mt][nt][2] + b0;
            float v11 = cacc[mt][nt][3] + b1;
            if (p.mode != 0) { v00 = siluf(v00); v01 = siluf(v01); v10 = siluf(v10); v11 = siluf(v11); }
            if (p.mode == 2) {
                unsigned hi, lo;
                split2(v00, v01, hi, lo);
                p.CH[(size_t)row0 * N2 + (col >> 1)] = hi;
                p.CL[(size_t)row0 * N2 + (col >> 1)] = lo;
                split2(v10, v11, hi, lo);
                p.CH[(size_t)(row0 + 8) * N2 + (col >> 1)] = hi;
                p.CL[(size_t)(row0 + 8) * N2 + (col >> 1)] = lo;
            } else {
                float2 r0 = {v00, v01};
                float2 r1 = {v10, v11};
                *reinterpret_cast<float2*>(p.Cf + (size_t)row0 * p.N + col) = r0;
                *reinterpret_cast<float2*>(p.Cf + (size_t)(row0 + 8) * p.N + col) = r1;
            }
        }
    }
}

#define GSMEM2 (STG * (2 * 128 * 12 * 4 + 2 * 64 * 12 * 4))   // 73728
#define GSMEM1 (STG * (2 * 64 * 12 * 4 + 2 * 64 * 12 * 4))    // 49152

__global__ void __launch_bounds__(256, 2)
k_bmma(GemmP p)
{
    extern __shared__ char smem[];
    bmma_body<2>(p, blockIdx.x, blockIdx.y, smem);
}

// dual GEMM (M-tile 64): blocks with x < split run p0, others p1
__global__ void __launch_bounds__(256, 2)
k_bmma2(GemmP p0, GemmP p1, int split)
{
    extern __shared__ char smem[];
    if ((int)blockIdx.x < split) bmma_body<1>(p0, blockIdx.x, blockIdx.y, smem);
    else                         bmma_body<1>(p1, blockIdx.x - split, blockIdx.y, smem);
}

// ---------------- k_contract: tpw(4608) x node tensors -> vec[pos][80] ---------
__global__ void __launch_bounds__(128)
k_contract(const float* __restrict__ h_full)
{
    __shared__ float s1[NODE_S];
    __shared__ float v1s[NODE_V * 3];
    __shared__ float bvi[NODE_V];
    __shared__ float uu[3];

    const int pos = blockIdx.x;
    if (pos >= g_count) return;
    const int tid = threadIdx.x;
    const int node = g_active[pos];
    const float* hf = h_full + (size_t)node * 160;

    if (tid < NODE_S) s1[tid] = hf[tid];
    if (tid < NODE_V * 3) v1s[tid] = hf[NODE_S + tid];
    if (tid < 3) uu[tid] = g_u[pos * 3 + tid];
    __syncthreads();
    if (tid < NODE_V)
        bvi[tid] = v1s[3 * tid] * uu[0] + v1s[3 * tid + 1] * uu[1] + v1s[3 * tid + 2] * uu[2];
    __syncthreads();

    const float* tp = g_tpw + (size_t)pos * WN;
    const float mul = g_mul[pos];

    if (tid < OUT_S) {
        int o = tid;
        float acc = 0.0f;
#pragma unroll 8
        for (int i = 0; i < NODE_S; i++) acc += s1[i] * tp[i * OUT_S + o];
#pragma unroll 8
        for (int i = 0; i < NODE_V; i++) acc += bvi[i] * tp[2048 + i * OUT_S + o];
        g_vec[(size_t)pos * OUT_DIM + o] = acc * mul;
    }
    if (tid >= 64 && tid < 112) {
        int t = tid - 64;
        int o = t & 15, c = t >> 4;      // o<16, c<3
        float sc = 0.0f, sd = 0.0f;
#pragma unroll 8
        for (int i = 0; i < NODE_S; i++) sc += s1[i] * tp[3072 + i * OUT_V + o];
#pragma unroll 8
        for (int i = 0; i < NODE_V; i++) sd += v1s[3 * i + c] * tp[4096 + i * OUT_V + o];
        float yv = SQRT3_F * uu[c];
        g_vec[(size_t)pos * OUT_DIM + OUT_S + o * 3 + c] = (sc * yv + sd) * mul;
    }
}

// ---------------- k_vabs1: deterministic per-batch partial reduce ---------------
__global__ void k_vabs1() {
    int b = blockIdx.x, ch = blockIdx.y, t = threadIdx.x;
    if (t >= OUT_DIM) return;
    float acc = 0.0f;
    int nbase = b * NN + ch * 32;
    for (int n = 0; n < 32; n++) {
        int node = nbase + n;
        if (g_winner[node] > 0)
            acc += g_vec[(size_t)g_posmap[node] * OUT_DIM + t];
    }
    g_vpart[(b * 4 + ch) * OUT_DIM + t] = acc;
}

// ---------------- k_invs: invariants (split bf16) + end-of-replay reset --------
__device__ __forceinline__ float vabs_of(int b, int j) {
    float a = g_vpart[(b * 4 + 0) * OUT_DIM + j];
    a += g_vpart[(b * 4 + 1) * OUT_DIM + j];
    a += g_vpart[(b * 4 + 2) * OUT_DIM + j];
    a += g_vpart[(b * 4 + 3) * OUT_DIM + j];
    return a;
}

__global__ void __launch_bounds__(256)
k_invs()
{
    int t = blockIdx.x * blockDim.x + threadIdx.x;
    if (t < FLAT) g_winner[t] = 0;
    if (t == 0)   g_count = 0;
    if (t >= ROWS3 * 24) return;
    int row = t / 24, jp = t - row * 24;
    int b = row >> 9, e = row & 511;
    float vals[2];
#pragma unroll
    for (int jj = 0; jj < 2; jj++) {
        int j = 2 * jp + jj;
        float v;
        if (j < OUT_S) {
            v = vabs_of(b, j) * g_scales[e * 48 + j];
        } else {
            int o = j - OUT_S;
            float s = g_scales[e * 48 + OUT_S + o];
            float x0 = vabs_of(b, OUT_S + o * 3 + 0) * s;
            float x1 = vabs_of(b, OUT_S + o * 3 + 1) * s;
            float x2 = vabs_of(b, OUT_S + o * 3 + 2) * s;
            v = sqrtf(x0 * x0 + x1 * x1 + x2 * x2 + 1e-12f);
        }
        vals[jj] = v;
    }
    unsigned hi, lo;
    split2(vals[0], vals[1], hi, lo);
    g_invH[row * 24 + jp] = hi;
    g_invL[row * 24 + jp] = lo;
}

// ---------------- launch ----------------
extern "C" void kernel_launch(void* const* d_in, const int* in_sizes, int n_in,
                              void* d_out, int out_size)
{
    const float* h        = (const float*)d_in[0];
    const float* h_full   = (const float*)d_in[1];
    const int*   z        = (const int*)  d_in[2];
    const float* e_feat   = (const float*)d_in[4];
    const int*   abs_idx  = (const int*)  d_in[5];
    const int*   att_dst  = (const int*)  d_in[6];
    const float* att_dist = (const float*)d_in[7];
    const float* att_vec  = (const float*)d_in[8];
    const float* w_zemb   = (const float*)d_in[9];
    const float* w1_rad   = (const float*)d_in[10];
    const float* b1_rad   = (const float*)d_in[11];
    const float* w2_rad   = (const float*)d_in[12];
    const float* b2_rad   = (const float*)d_in[13];
    const float* wg1      = (const float*)d_in[14];
    const float* bg1      = (const float*)d_in[15];
    const float* wg2      = (const float*)d_in[16];
    const float* bg2      = (const float*)d_in[17];
    const float* we1      = (const float*)d_in[18];
    const float* be1      = (const float*)d_in[19];
    const float* we2      = (const float*)d_in[20];
    const float* be2      = (const float*)d_in[21];
    const float* wo1      = (const float*)d_in[22];
    const float* bo1      = (const float*)d_in[23];
    const float* wo2      = (const float*)d_in[24];
    const float* bo2      = (const float*)d_in[25];
    const float* wo3      = (const float*)d_in[26];
    const float* bo3      = (const float*)d_in[27];
    float* out = (float*)d_out;

    float *d_ghid, *d_tpw;
    unsigned *d_winH, *d_winL, *d_ginH, *d_ginL, *d_hidH, *d_hidL;
    unsigned *d_invH, *d_invL, *d_x1H, *d_x1L, *d_x2H, *d_x2L;
    unsigned *d_wg1H, *d_wg1L, *d_w1H, *d_w1L, *d_w2H, *d_w2L;
    unsigned *d_wo1H, *d_wo1L, *d_wo2H, *d_wo2L, *d_wo3H, *d_wo3L;
    cudaGetSymbolAddress((void**)&d_ghid, g_ghid);
    cudaGetSymbolAddress((void**)&d_tpw,  g_tpw);
    cudaGetSymbolAddress((void**)&d_winH, g_winH);
    cudaGetSymbolAddress((void**)&d_winL, g_winL);
    cudaGetSymbolAddress((void**)&d_ginH, g_ginH);
    cudaGetSymbolAddress((void**)&d_ginL, g_ginL);
    cudaGetSymbolAddress((void**)&d_hidH, g_hidH);
    cudaGetSymbolAddress((void**)&d_hidL, g_hidL);
    cudaGetSymbolAddress((void**)&d_invH, g_invH);
    cudaGetSymbolAddress((void**)&d_invL, g_invL);
    cudaGetSymbolAddress((void**)&d_x1H,  g_x1H);
    cudaGetSymbolAddress((void**)&d_x1L,  g_x1L);
    cudaGetSymbolAddress((void**)&d_x2H,  g_x2H);
    cudaGetSymbolAddress((void**)&d_x2L,  g_x2L);
    cudaGetSymbolAddress((void**)&d_wg1H, g_wg1H);
    cudaGetSymbolAddress((void**)&d_wg1L, g_wg1L);
    cudaGetSymbolAddress((void**)&d_w1H,  g_w1H);
    cudaGetSymbolAddress((void**)&d_w1L,  g_w1L);
    cudaGetSymbolAddress((void**)&d_w2H,  g_w2H);
    cudaGetSymbolAddress((void**)&d_w2L,  g_w2L);
    cudaGetSymbolAddress((void**)&d_wo1H, g_wo1H);
    cudaGetSymbolAddress((void**)&d_wo1L, g_wo1L);
    cudaGetSymbolAddress((void**)&d_wo2H, g_wo2H);
    cudaGetSymbolAddress((void**)&d_wo2L, g_wo2L);
    cudaGetSymbolAddress((void**)&d_wo3H, g_wo3H);
    cudaGetSymbolAddress((void**)&d_wo3L, g_wo3L);

    cudaFuncSetAttribute(k_bmma,  cudaFuncAttributeMaxDynamicSharedMemorySize, GSMEM2);
    cudaFuncSetAttribute(k_bmma2, cudaFuncAttributeMaxDynamicSharedMemorySize, GSMEM1);

    // 1: edge scatter + weight split
    k_initw<<<(SEG5 + 255) / 256, 256>>>(att_dst, wg1, w1_rad, w2_rad, wo1, wo2, wo3);
    // 2: compact active nodes
    k_compact<<<(FLAT + 255) / 256, 256>>>();
    // 3: per-node input prep (warp-per-pos) + scales MLP
    k_prep<<<PREP_POS_BLOCKS + NEE, 128>>>(h, z, abs_idx, att_dist, att_vec, w_zemb,
                                           e_feat, we1, be1, we2, be2);

    GemmP pg = {d_ginH, d_ginL, d_wg1H, d_wg1L, bg1, d_ghid, nullptr, nullptr, 128, KGIN, 1};
    GemmP pr = {d_winH, d_winL, d_w1H, d_w1L, b1_rad, nullptr, d_hidH, d_hidL, 128, KWIN, 2};
    // 4 (PROFILED): fused gate (4096x128,K=288) + rad (4096x128,K=64), M-tile 64
    k_bmma2<<<dim3(4, NACT_MAX / 64), 256, GSMEM1>>>(pg, pr, 2);
    // 5
    k_gate2<<<NACT_MAX / 8, 256>>>(wg2, bg2);
    // 6: tpw = hid @ w2 + b2: 4096 x 4608, K=128
    GemmP pt = {d_hidH, d_hidL, d_w2H, d_w2L, b2_rad, d_tpw, nullptr, nullptr, WN, HIDN, 0};
    k_bmma<<<dim3(WN / 64, NACT_MAX / 128), 256, GSMEM2>>>(pt);
    // 7-8
    k_contract<<<NACT_MAX, 128>>>(h_full);
    k_vabs1<<<dim3(BB, 4), 80>>>();
    // 9: invariants + end-of-replay reset
    k_invs<<<(ROWS3 * 24 + 255) / 256, 256>>>();
    // 10-12: tail MLP
    GemmP p1 = {d_invH, d_invL, d_wo1H, d_wo1L, bo1, nullptr, d_x1H, d_x1L, 128, 48, 2};
    k_bmma<<<dim3(2, ROWS3 / 128), 256, GSMEM2>>>(p1);
    GemmP p2 = {d_x1H, d_x1L, d_wo2H, d_wo2L, bo2, nullptr, d_x2H, d_x2L, 128, HIDN, 2};
    k_bmma<<<dim3(2, ROWS3 / 128), 256, GSMEM2>>>(p2);
    GemmP p3 = {d_x2H, d_x2L, d_wo3H, d_wo3L, bo3, out, nullptr, nullptr, 256, HIDN, 0};
    k_bmma<<<dim3(4, ROWS3 / 128), 256, GSMEM2>>>(p3);
}